// round 11
// baseline (speedup 1.0000x reference)
#include <cuda_runtime.h>
#include <cstdint>
#include <math.h>

#define NNODES 8192
#define NEDGES 65536
#define NSURF  40000
#define NUNIQ  6000
#define NGRAPH 16
#define DIMF   1024
#define HID    64
#define EPSV   1e-5f
#define SLOPE  0.01f

// ---------------- scratch (device globals; referenced ONLY in device code) ----------------
__device__ float    g_feat[NNODES*DIMF];
__device__ float    g_acc [NNODES*DIMF];
__device__ unsigned g_agg [NNODES*DIMF];     // tf32 bits (A operand, row-major)
__device__ unsigned g_bw  [4*DIMF*DIMF];     // tf32 bits of lin_w (row-major, 4 layers)
__device__ float    g_gemm[NNODES*DIMF];
__device__ float    g_surfy[NSURF*HID];
__device__ float    g_ressum[NNODES*HID];
__device__ float    g_rescnt[NNODES];
__device__ float    g_s[NUNIQ*HID];
__device__ float    g_su[NNODES];
__device__ int      g_csru[NEDGES];
__device__ int      g_rowptr[NNODES+1];
__device__ float    g_stats [2*HID];
__device__ float    g_stats2[2*HID];
__device__ float    g_nf[NNODES*HID];
__device__ float    g_y2[NUNIQ*HID];
__device__ float    g_nssum[NGRAPH*HID];
__device__ float    g_nscnt[NGRAPH];

__device__ __forceinline__ float lk(float x){ return x >= 0.f ? x : SLOPE*x; }

__device__ __forceinline__ unsigned f2tf32(float f){
    unsigned r;
    asm("cvt.rna.tf32.f32 %0, %1;" : "=r"(r) : "f"(f));
    return r;
}

__device__ __forceinline__ float block_reduce_256(float v, float* sm){
    #pragma unroll
    for (int o=16;o>0;o>>=1) v += __shfl_xor_sync(0xffffffffu, v, o);
    int warp = threadIdx.x>>5, lane = threadIdx.x&31;
    if (lane==0) sm[warp]=v;
    __syncthreads();
    if (warp==0){
        v = (lane<8)? sm[lane] : 0.f;
        #pragma unroll
        for (int o=4;o>0;o>>=1) v += __shfl_xor_sync(0xffffffffu, v, o);
        if (lane==0) sm[0]=v;
    }
    __syncthreads();
    float r = sm[0];
    __syncthreads();
    return r;
}

__device__ __forceinline__ float block_reduce_max_256(float v, float* sm){
    #pragma unroll
    for (int o=16;o>0;o>>=1) v = fmaxf(v, __shfl_xor_sync(0xffffffffu, v, o));
    int warp = threadIdx.x>>5, lane = threadIdx.x&31;
    if (lane==0) sm[warp]=v;
    __syncthreads();
    if (warp==0){
        v = (lane<8)? sm[lane] : -1e30f;
        #pragma unroll
        for (int o=4;o>0;o>>=1) v = fmaxf(v, __shfl_xor_sync(0xffffffffu, v, o));
        if (lane==0) sm[0]=v;
    }
    __syncthreads();
    float r = sm[0];
    __syncthreads();
    return r;
}

// ---------------- launch 1: fused degree histogram + scan + CSR fill ----------------
__global__ void degfill_kernel(const int* __restrict__ ei){
    __shared__ int cnt[NNODES];
    __shared__ int sm[1024];
    int tid = threadIdx.x;
    for (int i=tid; i<NNODES; i+=1024) cnt[i]=0;
    __syncthreads();
    for (int e=tid; e<NEDGES; e+=1024) atomicAdd(&cnt[ei[NEDGES+e]], 1);
    __syncthreads();
    int base = tid*8;
    int loc[8]; int s=0;
    #pragma unroll
    for (int j=0;j<8;j++){ loc[j]=s; s += cnt[base+j]; }
    sm[tid]=s; __syncthreads();
    for (int off=1; off<1024; off<<=1){
        int t = (tid>=off) ? sm[tid-off] : 0;
        __syncthreads();
        sm[tid]+=t;
        __syncthreads();
    }
    int excl = sm[tid]-s;
    int st[8];
    #pragma unroll
    for (int j=0;j<8;j++){ st[j] = excl + loc[j]; g_rowptr[base+j] = st[j]; }
    if (tid==1023) g_rowptr[NNODES] = sm[1023];
    __syncthreads();
    #pragma unroll
    for (int j=0;j<8;j++) cnt[base+j] = st[j];
    __syncthreads();
    for (int e=tid; e<NEDGES; e+=1024){
        int v = ei[NEDGES+e];
        int p = atomicAdd(&cnt[v], 1);
        g_csru[p] = ei[e];
    }
}

// ---------------- launch 2: init copy + su(layer0) + weight conversion (row-major) ----------------
__global__ void init_su_kernel(const float* __restrict__ nf,
                               const float* __restrict__ a1,
                               const float* __restrict__ lw){
    int n = blockIdx.x, tid = threadIdx.x;
    float4 v = ((const float4*)nf)[(size_t)n*256+tid];
    ((float4*)g_feat)[(size_t)n*256+tid]=v;
    ((float4*)g_acc)[(size_t)n*256+tid]=v;
    if (tid < 128){
        size_t wi = (size_t)n*128 + tid;
        float4 wv = ((const float4*)lw)[wi];
        uint4 p;
        p.x=f2tf32(wv.x); p.y=f2tf32(wv.y); p.z=f2tf32(wv.z); p.w=f2tf32(wv.w);
        ((uint4*)g_bw)[wi] = p;
    }
    float4 a = ((const float4*)a1)[tid];
    float p = v.x*a.x + v.y*a.y + v.z*a.z + v.w*a.w;
    __shared__ float sm[32];
    p = block_reduce_256(p, sm);
    if (tid==0) g_su[n]=p;
}

// ---------------- launch 3: fused edge-softmax + aggregate; stores tf32 bits ----------------
__global__ void smagg_kernel(){
    int n = blockIdx.x, tid = threadIdx.x;
    int s = g_rowptr[n], e = g_rowptr[n+1];
    __shared__ float s_w[256]; __shared__ int s_u[256];
    __shared__ float red[32];
    float m = -1e30f;
    for (int j=s+tid; j<e; j+=256) m = fmaxf(m, g_su[g_csru[j]]);
    m = block_reduce_max_256(m, red);
    float lsum = 0.f;
    float4 acc = make_float4(0.f,0.f,0.f,0.f);
    const float4* F4 = (const float4*)g_feat;
    for (int base=s; base<e; base+=256){
        int j = base + tid;
        if (j<e){
            int u = g_csru[j];
            float ex = __expf(g_su[u] - m);
            s_w[tid]=ex; s_u[tid]=u; lsum += ex;
        }
        __syncthreads();
        int cnt = min(256, e-base);
        for (int t=0;t<cnt;t++){
            float wv = s_w[t]; int u = s_u[t];
            float4 f = F4[(size_t)u*256 + tid];
            acc.x += wv*f.x; acc.y += wv*f.y; acc.z += wv*f.z; acc.w += wv*f.w;
        }
        __syncthreads();
    }
    float total = block_reduce_256(lsum, red);
    if (total > 0.f){
        float inv = 1.f/total;
        acc.x*=inv; acc.y*=inv; acc.z*=inv; acc.w*=inv;
    }
    uint4 p;
    p.x=f2tf32(acc.x); p.y=f2tf32(acc.y); p.z=f2tf32(acc.z); p.w=f2tf32(acc.w);
    ((uint4*)g_agg)[(size_t)n*256 + tid] = p;
}

// ---------------- launch 4 (profiled): main tf32 GEMM ----------------
// 512 threads, 16 warps 4x4, warp tile 32x32 (acc=32 regs) -> 32 warps/SM.
#define STG  3
#define PA_  36
#define PB_  136
#define ASZ_ (128*PA_)
#define BSZ_ (32*PB_)
#define MAIN_SMEM (STG*(ASZ_+BSZ_)*4)

__global__ void __launch_bounds__(512,2) mma_main_kernel(int layer){
    extern __shared__ unsigned dyn[];
    unsigned* AsB = dyn;
    unsigned* BsB = dyn + STG*ASZ_;
    const unsigned* A = g_agg;
    const unsigned* B = g_bw + (size_t)layer*DIMF*DIMF;

    const int tid = threadIdx.x;
    const int warp = tid>>5, lane = tid&31;
    const int wm = warp>>2, wn = warp&3;       // 4x4 warps, warp tile 32x32
    const int gid = lane>>2, qid = lane&3;
    const int bm0 = blockIdx.y*128, bn0 = blockIdx.x*128;

    auto issue = [&](int it){
        unsigned* As = AsB + (it%STG)*ASZ_;
        unsigned* Bs = BsB + (it%STG)*BSZ_;
        int k0 = it*32;
        #pragma unroll
        for (int i=0;i<2;i++){
            int chunk = tid + i*512;           // 0..1023 A chunks of 16B
            int r = chunk>>3, c = (chunk&7)*4;
            unsigned dst = (unsigned)__cvta_generic_to_shared(&As[r*PA_+c]);
            asm volatile("cp.async.cg.shared.global [%0], [%1], 16;"
                         :: "r"(dst), "l"(A + (size_t)(bm0+r)*DIMF + k0 + c));
        }
        #pragma unroll
        for (int i=0;i<2;i++){
            int chunk = tid + i*512;           // 0..1023 B chunks
            int r = chunk>>5, c = (chunk&31)*4;
            unsigned dst = (unsigned)__cvta_generic_to_shared(&Bs[r*PB_+c]);
            asm volatile("cp.async.cg.shared.global [%0], [%1], 16;"
                         :: "r"(dst), "l"(B + (size_t)(k0+r)*DIMF + bn0 + c));
        }
        asm volatile("cp.async.commit_group;" ::: "memory");
    };

    float acc[2][4][4];
    #pragma unroll
    for (int i=0;i<2;i++)
        #pragma unroll
        for (int j=0;j<4;j++)
            #pragma unroll
            for (int q=0;q<4;q++) acc[i][j][q]=0.f;

    issue(0); issue(1);

    const int NIT = DIMF/32;
    for (int it=0; it<NIT; it++){
        asm volatile("cp.async.wait_group 1;" ::: "memory");
        __syncthreads();
        if (it+2 < NIT) issue(it+2);
        const unsigned* curA = AsB + (it%STG)*ASZ_;
        const unsigned* curB = BsB + (it%STG)*BSZ_;
        #pragma unroll
        for (int kk=0; kk<4; kk++){
            unsigned af[2][4], bf[4][2];
            #pragma unroll
            for (int i=0;i<2;i++){
                int r0 = wm*32 + i*16 + gid;
                int c0 = kk*8 + qid;
                af[i][0]=curA[ r0   *PA_ + c0  ];
                af[i][1]=curA[(r0+8)*PA_ + c0  ];
                af[i][2]=curA[ r0   *PA_ + c0+4];
                af[i][3]=curA[(r0+8)*PA_ + c0+4];
            }
            #pragma unroll
            for (int j=0;j<4;j++){
                int cc = wn*32 + j*8 + gid;
                bf[j][0]=curB[(kk*8+qid  )*PB_ + cc];
                bf[j][1]=curB[(kk*8+qid+4)*PB_ + cc];
            }
            #pragma unroll
            for (int i=0;i<2;i++)
                #pragma unroll
                for (int j=0;j<4;j++){
                    asm volatile(
                        "mma.sync.aligned.m16n8k8.row.col.f32.tf32.tf32.f32 "
                        "{%0,%1,%2,%3}, {%4,%5,%6,%7}, {%8,%9}, {%0,%1,%2,%3};"
                        : "+f"(acc[i][j][0]), "+f"(acc[i][j][1]),
                          "+f"(acc[i][j][2]), "+f"(acc[i][j][3])
                        : "r"(af[i][0]), "r"(af[i][1]), "r"(af[i][2]), "r"(af[i][3]),
                          "r"(bf[j][0]), "r"(bf[j][1]));
                }
        }
    }
    #pragma unroll
    for (int i=0;i<2;i++){
        int r0 = bm0 + wm*32 + i*16 + gid;
        #pragma unroll
        for (int j=0;j<4;j++){
            int cc = bn0 + wn*32 + j*8 + qid*2;
            float2 v0, v1;
            v0.x = acc[i][j][0]; v0.y = acc[i][j][1];
            v1.x = acc[i][j][2]; v1.y = acc[i][j][3];
            *(float2*)(g_gemm + (size_t) r0   *DIMF + cc) = v0;
            *(float2*)(g_gemm + (size_t)(r0+8)*DIMF + cc) = v1;
        }
    }
}

// ---------------- hid GEMM (small; register-staged path) ----------------
template<int BM,int BN,int BK,int WM,int WN,bool BIAS>
__device__ __forceinline__ void mma_body(
        const float* __restrict__ A, const float* __restrict__ B,
        float* __restrict__ C, int N, int K,
        float alpha, const float* __restrict__ bias,
        unsigned* As, unsigned* Bs){
    constexpr int MT = WM/16, NT = WN/8, KT = BK/8;
    constexpr int WARPS_N = BN/WN;
    constexpr int PA = BK+4;
    constexpr int PB = BN+8;
    constexpr int AREG = BM*BK/1024;
    constexpr int BREG = BK*BN/1024;

    const int tid = threadIdx.x;
    const int warp = tid>>5, lane = tid&31;
    const int wm = warp / WARPS_N, wn = warp % WARPS_N;
    const int gid = lane>>2, qid = lane&3;
    const int bm0 = blockIdx.y*BM, bn0 = blockIdx.x*BN;

    float4 ra[AREG], rb[BREG];

    auto ldg_tile = [&](int k0){
        #pragma unroll
        for (int a=0;a<AREG;a++){
            int i = tid*4 + a*1024;
            int r = i/BK, c = i%BK;
            ra[a] = *(const float4*)(A + (size_t)(bm0+r)*K + k0 + c);
        }
        #pragma unroll
        for (int b=0;b<BREG;b++){
            int i = tid*4 + b*1024;
            int r = i/BN, c = i%BN;
            rb[b] = *(const float4*)(B + (size_t)(k0+r)*N + bn0 + c);
        }
    };
    auto sts_tile = [&](){
        #pragma unroll
        for (int a=0;a<AREG;a++){
            int i = tid*4 + a*1024;
            int r = i/BK, c = i%BK;
            uint4 p;
            p.x=f2tf32(ra[a].x); p.y=f2tf32(ra[a].y);
            p.z=f2tf32(ra[a].z); p.w=f2tf32(ra[a].w);
            *(uint4*)&As[r*PA+c] = p;
        }
        #pragma unroll
        for (int b=0;b<BREG;b++){
            int i = tid*4 + b*1024;
            int r = i/BN, c = i%BN;
            uint4 p;
            p.x=f2tf32(rb[b].x); p.y=f2tf32(rb[b].y);
            p.z=f2tf32(rb[b].z); p.w=f2tf32(rb[b].w);
            *(uint4*)&Bs[r*PB+c] = p;
        }
    };

    float acc[MT][NT][4];
    #pragma unroll
    for (int i=0;i<MT;i++)
        #pragma unroll
        for (int j=0;j<NT;j++)
            #pragma unroll
            for (int q=0;q<4;q++) acc[i][j][q]=0.f;

    ldg_tile(0);
    sts_tile();
    __syncthreads();

    const int NIT = K/BK;
    for (int it=0; it<NIT; it++){
        if (it+1 < NIT) ldg_tile((it+1)*BK);
        #pragma unroll
        for (int kk=0; kk<KT; kk++){
            unsigned af[MT][4], bf[NT][2];
            #pragma unroll
            for (int i=0;i<MT;i++){
                int r0 = wm*WM + i*16 + gid;
                int c0 = kk*8 + qid;
                af[i][0]=As[ r0   *PA + c0  ];
                af[i][1]=As[(r0+8)*PA + c0  ];
                af[i][2]=As[ r0   *PA + c0+4];
                af[i][3]=As[(r0+8)*PA + c0+4];
            }
            #pragma unroll
            for (int j=0;j<NT;j++){
                int cc = wn*WN + j*8 + gid;
                bf[j][0]=Bs[(kk*8+qid  )*PB + cc];
                bf[j][1]=Bs[(kk*8+qid+4)*PB + cc];
            }
            #pragma unroll
            for (int i=0;i<MT;i++)
                #pragma unroll
                for (int j=0;j<NT;j++){
                    asm volatile(
                        "mma.sync.aligned.m16n8k8.row.col.f32.tf32.tf32.f32 "
                        "{%0,%1,%2,%3}, {%4,%5,%6,%7}, {%8,%9}, {%0,%1,%2,%3};"
                        : "+f"(acc[i][j][0]), "+f"(acc[i][j][1]),
                          "+f"(acc[i][j][2]), "+f"(acc[i][j][3])
                        : "r"(af[i][0]), "r"(af[i][1]), "r"(af[i][2]), "r"(af[i][3]),
                          "r"(bf[j][0]), "r"(bf[j][1]));
                }
        }
        __syncthreads();
        if (it+1 < NIT){
            sts_tile();
            __syncthreads();
        }
    }
    #pragma unroll
    for (int i=0;i<MT;i++){
        int r0 = bm0 + wm*WM + i*16 + gid;
        #pragma unroll
        for (int j=0;j<NT;j++){
            int cc = bn0 + wn*WN + j*8 + qid*2;
            float b0 = BIAS ? bias[cc] : 0.f;
            float b1 = BIAS ? bias[cc+1] : 0.f;
            float2 v0, v1;
            v0.x = alpha*acc[i][j][0] + b0;
            v0.y = alpha*acc[i][j][1] + b1;
            v1.x = alpha*acc[i][j][2] + b0;
            v1.y = alpha*acc[i][j][3] + b1;
            *(float2*)(C + (size_t) r0   *N + cc) = v0;
            *(float2*)(C + (size_t)(r0+8)*N + cc) = v1;
        }
    }
}

#define HID_SMEM ((64*36 + 32*72)*4)
__global__ void __launch_bounds__(256) mma_hid_kernel(const float* __restrict__ Bw,
                                                      const float* __restrict__ bias){
    extern __shared__ unsigned dyn[];
    unsigned* As = dyn;
    unsigned* Bs = dyn + 64*36;
    mma_body<64,64,32,16,32,true>(g_acc, Bw, g_nf, HID, DIMF,
                                  0.2f, bias, As, Bs);
}

// ---------------- launch 5 (per layer): LN + leaky + feat/acc update + next su ----------------
__global__ void ln_su_kernel(const float* __restrict__ linb,
                             const float* __restrict__ lng,
                             const float* __restrict__ lnb,
                             const float* __restrict__ a1next){
    int n = blockIdx.x, tid = threadIdx.x;
    float4 x = ((const float4*)g_gemm)[(size_t)n*256+tid];
    float4 bb = ((const float4*)linb)[tid];
    x.x+=bb.x; x.y+=bb.y; x.z+=bb.z; x.w+=bb.w;
    __shared__ float sm[32];
    float s = x.x+x.y+x.z+x.w;
    s = block_reduce_256(s, sm);
    float mu = s*(1.f/1024.f);
    float d0=x.x-mu, d1=x.y-mu, d2=x.z-mu, d3=x.w-mu;
    float q = d0*d0+d1*d1+d2*d2+d3*d3;
    q = block_reduce_256(q, sm);
    float r = rsqrtf(q*(1.f/1024.f)+EPSV);
    float4 gg = ((const float4*)lng)[tid];
    float4 b2 = ((const float4*)lnb)[tid];
    float4 y;
    y.x = lk(gg.x*d0*r + b2.x);
    y.y = lk(gg.y*d1*r + b2.y);
    y.z = lk(gg.z*d2*r + b2.z);
    y.w = lk(gg.w*d3*r + b2.w);
    ((float4*)g_feat)[(size_t)n*256+tid] = y;
    float4 a = ((float4*)g_acc)[(size_t)n*256+tid];
    a.x+=y.x; a.y+=y.y; a.z+=y.z; a.w+=y.w;
    ((float4*)g_acc)[(size_t)n*256+tid] = a;
    if (a1next){
        float4 av = ((const float4*)a1next)[tid];
        float p = y.x*av.x + y.y*av.y + y.z*av.z + y.w*av.w;
        p = block_reduce_256(p, sm);
        if (tid==0) g_su[n]=p;
    }
}

// ---------------- zeroing (surface/ns branch only) ----------------
__global__ void zero_kernel(){
    int i = blockIdx.x*256 + threadIdx.x;
    if (i < NNODES*HID) g_ressum[i] = 0.f;
    if (i < NNODES) g_rescnt[i]=0.f;
    if (i < 2*HID){ g_stats[i]=0.f; g_stats2[i]=0.f; }
    if (i < NGRAPH*HID) g_nssum[i]=0.f;
    if (i < NGRAPH) g_nscnt[i]=0.f;
}

// ---------------- surface path ----------------
__global__ void surf_lin_kernel(const float* __restrict__ sf,
                                const float* __restrict__ W,
                                const float* __restrict__ b){
    int c  = threadIdx.x & 63;
    int ry = threadIdx.x >> 6;
    int row0 = blockIdx.x * 64;
    float w0=W[c], w1=W[64+c], w2=W[128+c], bc=b[c];
    float ls=0.f, lss=0.f;
    for (int r=ry; r<64; r+=4){
        int row = row0 + r;
        float x0=sf[row*3], x1=sf[row*3+1], x2=sf[row*3+2];
        float y = fmaf(x0,w0, fmaf(x1,w1, fmaf(x2,w2, bc)));
        g_surfy[row*64+c]=y; ls+=y; lss+=y*y;
    }
    __shared__ float ss[256], sq[256];
    ss[threadIdx.x]=ls; sq[threadIdx.x]=lss;
    __syncthreads();
    if (ry==0){
        float t  = ss[c]+ss[64+c]+ss[128+c]+ss[192+c];
        float t2 = sq[c]+sq[64+c]+sq[128+c]+sq[192+c];
        atomicAdd(&g_stats[c], t);
        atomicAdd(&g_stats[64+c], t2);
    }
}

__global__ void finalize_stats_kernel(int which, float n){
    float* st = which ? g_stats2 : g_stats;
    int c = threadIdx.x;
    float mu  = st[c] / n;
    float var = st[64+c]/n - mu*mu;
    st[c]   = mu;
    st[64+c]= rsqrtf(fmaxf(var,0.f)+EPSV);
}

__global__ void surf_norm_scatter_kernel(const int* __restrict__ surf_res,
                                         const float* __restrict__ g,
                                         const float* __restrict__ beta){
    int idx = blockIdx.x*256 + threadIdx.x;
    int row = idx >> 6, c = idx & 63;
    float y = g_surfy[idx];
    float v = lk(g[c]*(y - g_stats[c])*g_stats[64+c] + beta[c]);
    int t = surf_res[row];
    atomicAdd(&g_ressum[t*64 + c], v);
    if (c==0) atomicAdd(&g_rescnt[t], 1.f);
}

__global__ void gather_s_kernel(const int* __restrict__ uniq){
    int idx = blockIdx.x*256 + threadIdx.x;
    int i = idx >> 6, c = idx & 63;
    int u = uniq[i];
    g_s[idx] = g_ressum[u*64+c] / fmaxf(g_rescnt[u], 1.f);
}

// ---------------- final heads ----------------
__global__ void prot_kernel(const float* __restrict__ g,
                            const float* __restrict__ b,
                            float* __restrict__ out){
    int gr = blockIdx.x, c = threadIdx.x;
    const float* base = g_nf + (size_t)gr*512*64;
    float s = 0.f;
    for (int r=0;r<512;r++) s += base[r*64+c];
    float x = s*(1.f/512.f);
    __shared__ float sm[64];
    __shared__ float s_mu, s_r;
    sm[c]=x; __syncthreads();
    if (c==0){ float t=0.f; for (int i=0;i<64;i++) t+=sm[i]; s_mu=t*(1.f/64.f); }
    __syncthreads();
    float d = x - s_mu;
    sm[c]=d*d; __syncthreads();
    if (c==0){ float t=0.f; for (int i=0;i<64;i++) t+=sm[i]; s_r=rsqrtf(t*(1.f/64.f)+EPSV); }
    __syncthreads();
    out[gr*64+c] = lk(g[c]*d*s_r + b[c]);
}

__global__ void ns_a_kernel(const int* __restrict__ uniq,
                            const float* __restrict__ dw,
                            const float* __restrict__ db){
    __shared__ float s_wd[128*64];
    __shared__ float z_s[128];
    int tid = threadIdx.x;
    for (int i=tid; i<128*64; i+=64) s_wd[i]=dw[i];
    float bc = db[tid];
    float ls=0.f, lss=0.f;
    __syncthreads();
    int row0 = blockIdx.x*64;
    for (int r=0;r<64;r++){
        int row = row0 + r;
        if (row >= NUNIQ) break;
        z_s[tid]      = g_nf[(size_t)uniq[row]*64 + tid];
        z_s[64+tid]   = g_s[(size_t)row*64 + tid];
        __syncthreads();
        float y = bc;
        #pragma unroll 8
        for (int k=0;k<128;k++) y = fmaf(z_s[k], s_wd[k*64+tid], y);
        g_y2[(size_t)row*64+tid] = y;
        ls += y; lss += y*y;
        __syncthreads();
    }
    atomicAdd(&g_stats2[tid], ls);
    atomicAdd(&g_stats2[64+tid], lss);
}

__global__ void ns_norm_scatter_kernel(const int* __restrict__ res_batch,
                                       const float* __restrict__ g,
                                       const float* __restrict__ beta){
    int idx = blockIdx.x*256 + threadIdx.x;
    int row = idx >> 6, c = idx & 63;
    float y = g_y2[idx];
    float v = lk(g[c]*(y - g_stats2[c])*g_stats2[64+c] + beta[c]);
    int t = res_batch[row];
    atomicAdd(&g_nssum[t*64 + c], v);
    if (c==0) atomicAdd(&g_nscnt[t], 1.f);
}

__global__ void ns_final_kernel(const float* __restrict__ bng,
                                const float* __restrict__ bnb,
                                float* __restrict__ out){
    int tid = threadIdx.x;
    int gr = tid >> 6, c = tid & 63;
    float v = g_nssum[tid] / fmaxf(g_nscnt[gr], 1.f);
    __shared__ float sm[1024];
    __shared__ float s_mu[64], s_r[64];
    sm[tid]=v; __syncthreads();
    if (gr==0){
        float t=0.f, t2=0.f;
        for (int r=0;r<16;r++){ float x=sm[r*64+c]; t+=x; t2+=x*x; }
        float mu = t*(1.f/16.f);
        s_mu[c]=mu;
        s_r[c]=rsqrtf(fmaxf(t2*(1.f/16.f)-mu*mu,0.f)+EPSV);
    }
    __syncthreads();
    out[16*64 + tid] = lk(bng[c]*(v - s_mu[c])*s_r[c] + bnb[c]);
}

// ---------------- host ----------------
extern "C" void kernel_launch(void* const* d_in, const int* in_sizes, int n_in,
                              void* d_out, int out_size){
    const int*   ei         = (const int*)  d_in[0];
    const float* n_feats    = (const float*)d_in[1];
    const float* surf_feats = (const float*)d_in[3];
    const int*   surf_res   = (const int*)  d_in[4];
    const int*   res_batch  = (const int*)  d_in[5];
    const int*   uniq       = (const int*)  d_in[6];
    const float* surf_up_w  = (const float*)d_in[7];
    const float* surf_up_b  = (const float*)d_in[8];
    const float* surf_up_g  = (const float*)d_in[9];
    const float* surf_up_be = (const float*)d_in[10];
    const float* a_w        = (const float*)d_in[11];
    const float* lin_w      = (const float*)d_in[12];
    const float* lin_b      = (const float*)d_in[13];
    const float* ln_g       = (const float*)d_in[14];
    const float* ln_b       = (const float*)d_in[15];
    const float* hid_w      = (const float*)d_in[16];
    const float* hid_b      = (const float*)d_in[17];
    const float* down_w     = (const float*)d_in[18];
    const float* down_b     = (const float*)d_in[19];
    const float* down_g     = (const float*)d_in[20];
    const float* down_be    = (const float*)d_in[21];
    const float* prot_ln_g  = (const float*)d_in[22];
    const float* prot_ln_b  = (const float*)d_in[23];
    const float* surf_bn_g  = (const float*)d_in[24];
    const float* surf_bn_b  = (const float*)d_in[25];
    float* out = (float*)d_out;

    cudaFuncSetAttribute(mma_main_kernel,
                         cudaFuncAttributeMaxDynamicSharedMemorySize, MAIN_SMEM);
    cudaFuncSetAttribute(mma_hid_kernel,
                         cudaFuncAttributeMaxDynamicSharedMemorySize, HID_SMEM);

    degfill_kernel<<<1, 1024>>>(ei);                                // 1
    init_su_kernel<<<NNODES, 256>>>(n_feats, a_w, lin_w);           // 2

    for (int l=0; l<4; l++){
        smagg_kernel<<<NNODES, 256>>>();                            // 3
        mma_main_kernel<<<dim3(DIMF/128, NNODES/128), 512, MAIN_SMEM>>>(l); // 4 <- profiled
        const float* a1n = (l<3) ? (a_w + (size_t)(l+1)*2*DIMF) : nullptr;
        ln_su_kernel<<<NNODES, 256>>>(lin_b + (size_t)l*DIMF,       // 5
                                      ln_g + (size_t)l*DIMF,
                                      ln_b + (size_t)l*DIMF, a1n);
    }

    mma_hid_kernel<<<dim3(1, NNODES/64), 256, HID_SMEM>>>(hid_w, hid_b);
    prot_kernel<<<NGRAPH, 64>>>(prot_ln_g, prot_ln_b, out);

    zero_kernel<<<(NNODES*HID)/256, 256>>>();
    surf_lin_kernel<<<NSURF/64, 256>>>(surf_feats, surf_up_w, surf_up_b);
    finalize_stats_kernel<<<1,64>>>(0, (float)NSURF);
    surf_norm_scatter_kernel<<<(NSURF*HID)/256, 256>>>(surf_res, surf_up_g, surf_up_be);
    gather_s_kernel<<<(NUNIQ*HID)/256, 256>>>(uniq);

    ns_a_kernel<<<(NUNIQ+63)/64, 64>>>(uniq, down_w, down_b);
    finalize_stats_kernel<<<1,64>>>(1, (float)NUNIQ);
    ns_norm_scatter_kernel<<<(NUNIQ*HID)/256, 256>>>(res_batch, down_g, down_be);
    ns_final_kernel<<<1,1024>>>(surf_bn_g, surf_bn_b, out);
}

// round 12
// speedup vs baseline: 1.0317x; 1.0317x over previous
#include <cuda_runtime.h>
#include <cstdint>
#include <math.h>

#define NNODES 8192
#define NEDGES 65536
#define NSURF  40000
#define NUNIQ  6000
#define NGRAPH 16
#define DIMF   1024
#define HID    64
#define EPSV   1e-5f
#define SLOPE  0.01f

// ---------------- scratch (device globals; referenced ONLY in device code) ----------------
__device__ float    g_feat[NNODES*DIMF];
__device__ float    g_acc [NNODES*DIMF];
__device__ unsigned g_agg [NNODES*DIMF];     // tf32 bits (A operand, row-major)
__device__ unsigned g_bw  [4*DIMF*DIMF];     // tf32 bits of lin_w (row-major, 4 layers)
__device__ float    g_gemm[NNODES*DIMF];
__device__ float    g_surfy[NSURF*HID];
__device__ float    g_ressum[NNODES*HID];
__device__ float    g_rescnt[NNODES];
__device__ float    g_su[NNODES];
__device__ int      g_csru[NEDGES];
__device__ int      g_rowptr[NNODES+1];
__device__ float    g_stats [2*HID];
__device__ float    g_stats2[2*HID];
__device__ float    g_nf[NNODES*HID];
__device__ float    g_y2[NUNIQ*HID];
__device__ float    g_nssum[NGRAPH*HID];
__device__ float    g_nscnt[NGRAPH];

__device__ __forceinline__ float lk(float x){ return x >= 0.f ? x : SLOPE*x; }

__device__ __forceinline__ unsigned f2tf32(float f){
    unsigned r;
    asm("cvt.rna.tf32.f32 %0, %1;" : "=r"(r) : "f"(f));
    return r;
}

__device__ __forceinline__ float block_reduce_256(float v, float* sm){
    #pragma unroll
    for (int o=16;o>0;o>>=1) v += __shfl_xor_sync(0xffffffffu, v, o);
    int warp = threadIdx.x>>5, lane = threadIdx.x&31;
    if (lane==0) sm[warp]=v;
    __syncthreads();
    if (warp==0){
        v = (lane<8)? sm[lane] : 0.f;
        #pragma unroll
        for (int o=4;o>0;o>>=1) v += __shfl_xor_sync(0xffffffffu, v, o);
        if (lane==0) sm[0]=v;
    }
    __syncthreads();
    float r = sm[0];
    __syncthreads();
    return r;
}

__device__ __forceinline__ float block_reduce_max_256(float v, float* sm){
    #pragma unroll
    for (int o=16;o>0;o>>=1) v = fmaxf(v, __shfl_xor_sync(0xffffffffu, v, o));
    int warp = threadIdx.x>>5, lane = threadIdx.x&31;
    if (lane==0) sm[warp]=v;
    __syncthreads();
    if (warp==0){
        v = (lane<8)? sm[lane] : -1e30f;
        #pragma unroll
        for (int o=4;o>0;o>>=1) v = fmaxf(v, __shfl_xor_sync(0xffffffffu, v, o));
        if (lane==0) sm[0]=v;
    }
    __syncthreads();
    float r = sm[0];
    __syncthreads();
    return r;
}

// ---------------- launch 1: zeroing (surface/ns branch consumers) ----------------
__global__ void zero_kernel(){
    int i = blockIdx.x*256 + threadIdx.x;
    if (i < NNODES*HID) g_ressum[i] = 0.f;
    if (i < NNODES) g_rescnt[i]=0.f;
    if (i < 2*HID){ g_stats[i]=0.f; g_stats2[i]=0.f; }
    if (i < NGRAPH*HID) g_nssum[i]=0.f;
    if (i < NGRAPH) g_nscnt[i]=0.f;
}

// ---------------- launch 2: fused degree histogram + scan + CSR fill ----------------
__global__ void degfill_kernel(const int* __restrict__ ei){
    __shared__ int cnt[NNODES];
    __shared__ int sm[1024];
    int tid = threadIdx.x;
    for (int i=tid; i<NNODES; i+=1024) cnt[i]=0;
    __syncthreads();
    for (int e=tid; e<NEDGES; e+=1024) atomicAdd(&cnt[ei[NEDGES+e]], 1);
    __syncthreads();
    int base = tid*8;
    int loc[8]; int s=0;
    #pragma unroll
    for (int j=0;j<8;j++){ loc[j]=s; s += cnt[base+j]; }
    sm[tid]=s; __syncthreads();
    for (int off=1; off<1024; off<<=1){
        int t = (tid>=off) ? sm[tid-off] : 0;
        __syncthreads();
        sm[tid]+=t;
        __syncthreads();
    }
    int excl = sm[tid]-s;
    int st[8];
    #pragma unroll
    for (int j=0;j<8;j++){ st[j] = excl + loc[j]; g_rowptr[base+j] = st[j]; }
    if (tid==1023) g_rowptr[NNODES] = sm[1023];
    __syncthreads();
    #pragma unroll
    for (int j=0;j<8;j++) cnt[base+j] = st[j];
    __syncthreads();
    for (int e=tid; e<NEDGES; e+=1024){
        int v = ei[NEDGES+e];
        int p = atomicAdd(&cnt[v], 1);
        g_csru[p] = ei[e];
    }
}

// ---------------- launch 3: init copy + su(layer0) + weight conversion ----------------
__global__ void init_su_kernel(const float* __restrict__ nf,
                               const float* __restrict__ a1,
                               const float* __restrict__ lw){
    int n = blockIdx.x, tid = threadIdx.x;
    float4 v = ((const float4*)nf)[(size_t)n*256+tid];
    ((float4*)g_feat)[(size_t)n*256+tid]=v;
    ((float4*)g_acc)[(size_t)n*256+tid]=v;
    if (tid < 128){
        size_t wi = (size_t)n*128 + tid;
        float4 wv = ((const float4*)lw)[wi];
        uint4 p;
        p.x=f2tf32(wv.x); p.y=f2tf32(wv.y); p.z=f2tf32(wv.z); p.w=f2tf32(wv.w);
        ((uint4*)g_bw)[wi] = p;
    }
    float4 a = ((const float4*)a1)[tid];
    float p = v.x*a.x + v.y*a.y + v.z*a.z + v.w*a.w;
    __shared__ float sm[32];
    p = block_reduce_256(p, sm);
    if (tid==0) g_su[n]=p;
}

// ---------------- launch 4 (profiled): fused edge-softmax + aggregate ----------------
__global__ void smagg_kernel(){
    int n = blockIdx.x, tid = threadIdx.x;
    int s = g_rowptr[n], e = g_rowptr[n+1];
    __shared__ float s_w[256]; __shared__ int s_u[256];
    __shared__ float red[32];
    float m = -1e30f;
    for (int j=s+tid; j<e; j+=256) m = fmaxf(m, g_su[g_csru[j]]);
    m = block_reduce_max_256(m, red);
    float lsum = 0.f;
    float4 acc = make_float4(0.f,0.f,0.f,0.f);
    const float4* F4 = (const float4*)g_feat;
    for (int base=s; base<e; base+=256){
        int j = base + tid;
        if (j<e){
            int u = g_csru[j];
            float ex = __expf(g_su[u] - m);
            s_w[tid]=ex; s_u[tid]=u; lsum += ex;
        }
        __syncthreads();
        int cnt = min(256, e-base);
        for (int t=0;t<cnt;t++){
            float wv = s_w[t]; int u = s_u[t];
            float4 f = F4[(size_t)u*256 + tid];
            acc.x += wv*f.x; acc.y += wv*f.y; acc.z += wv*f.z; acc.w += wv*f.w;
        }
        __syncthreads();
    }
    float total = block_reduce_256(lsum, red);
    if (total > 0.f){
        float inv = 1.f/total;
        acc.x*=inv; acc.y*=inv; acc.z*=inv; acc.w*=inv;
    }
    uint4 p;
    p.x=f2tf32(acc.x); p.y=f2tf32(acc.y); p.z=f2tf32(acc.z); p.w=f2tf32(acc.w);
    ((uint4*)g_agg)[(size_t)n*256 + tid] = p;
}

// ---------------- launch 5: main tf32 GEMM (round-8 config: 256 thr, 2 blk/SM) ----------------
#define STG  3
#define PA_  36
#define PB_  136
#define ASZ_ (128*PA_)
#define BSZ_ (32*PB_)
#define MAIN_SMEM (STG*(ASZ_+BSZ_)*4)

__global__ void __launch_bounds__(256,2) mma_main_kernel(int layer){
    extern __shared__ unsigned dyn[];
    unsigned* AsB = dyn;
    unsigned* BsB = dyn + STG*ASZ_;
    const unsigned* A = g_agg;
    const unsigned* B = g_bw + (size_t)layer*DIMF*DIMF;

    const int tid = threadIdx.x;
    const int warp = tid>>5, lane = tid&31;
    const int wm = warp>>2, wn = warp&3;         // 2x4 warps, warp tile 64x32
    const int gid = lane>>2, qid = lane&3;
    const int bm0 = blockIdx.y*128, bn0 = blockIdx.x*128;

    const int ca = (tid*4)&31,  ra0 = tid>>3;
    const int cb = (tid*4)&127, rb0 = tid>>5;

    auto issue = [&](int it){
        unsigned* As = AsB + (it%STG)*ASZ_;
        unsigned* Bs = BsB + (it%STG)*BSZ_;
        int k0 = it*32;
        #pragma unroll
        for (int a=0;a<4;a++){
            int r = ra0 + a*32;
            unsigned dst = (unsigned)__cvta_generic_to_shared(&As[r*PA_+ca]);
            asm volatile("cp.async.cg.shared.global [%0], [%1], 16;"
                         :: "r"(dst), "l"(A + (size_t)(bm0+r)*DIMF + k0 + ca));
        }
        #pragma unroll
        for (int b=0;b<4;b++){
            int r = rb0 + b*8;
            unsigned dst = (unsigned)__cvta_generic_to_shared(&Bs[r*PB_+cb]);
            asm volatile("cp.async.cg.shared.global [%0], [%1], 16;"
                         :: "r"(dst), "l"(B + (size_t)(k0+r)*DIMF + bn0 + cb));
        }
        asm volatile("cp.async.commit_group;" ::: "memory");
    };

    float acc[4][4][4];
    #pragma unroll
    for (int i=0;i<4;i++)
        #pragma unroll
        for (int j=0;j<4;j++)
            #pragma unroll
            for (int q=0;q<4;q++) acc[i][j][q]=0.f;

    issue(0); issue(1);

    unsigned af[2][4][4], bf[2][4][2];

    const int NIT = DIMF/32;
    for (int it=0; it<NIT; it++){
        asm volatile("cp.async.wait_group 1;" ::: "memory");
        __syncthreads();
        if (it+2 < NIT) issue(it+2);
        const unsigned* curA = AsB + (it%STG)*ASZ_;
        const unsigned* curB = BsB + (it%STG)*BSZ_;

        #pragma unroll
        for (int i=0;i<4;i++){
            int r0 = wm*64 + i*16 + gid;
            af[0][i][0]=curA[ r0   *PA_ + qid  ];
            af[0][i][1]=curA[(r0+8)*PA_ + qid  ];
            af[0][i][2]=curA[ r0   *PA_ + qid+4];
            af[0][i][3]=curA[(r0+8)*PA_ + qid+4];
        }
        #pragma unroll
        for (int j=0;j<4;j++){
            int cc = wn*32 + j*8 + gid;
            bf[0][j][0]=curB[(qid  )*PB_ + cc];
            bf[0][j][1]=curB[(qid+4)*PB_ + cc];
        }

        #pragma unroll
        for (int kk=0; kk<4; kk++){
            const int cur = kk&1, nxt = cur^1;
            if (kk<3){
                int c0 = (kk+1)*8 + qid;
                #pragma unroll
                for (int i=0;i<4;i++){
                    int r0 = wm*64 + i*16 + gid;
                    af[nxt][i][0]=curA[ r0   *PA_ + c0  ];
                    af[nxt][i][1]=curA[(r0+8)*PA_ + c0  ];
                    af[nxt][i][2]=curA[ r0   *PA_ + c0+4];
                    af[nxt][i][3]=curA[(r0+8)*PA_ + c0+4];
                }
                #pragma unroll
                for (int j=0;j<4;j++){
                    int cc = wn*32 + j*8 + gid;
                    bf[nxt][j][0]=curB[((kk+1)*8+qid  )*PB_ + cc];
                    bf[nxt][j][1]=curB[((kk+1)*8+qid+4)*PB_ + cc];
                }
            }
            #pragma unroll
            for (int i=0;i<4;i++)
                #pragma unroll
                for (int j=0;j<4;j++){
                    asm volatile(
                        "mma.sync.aligned.m16n8k8.row.col.f32.tf32.tf32.f32 "
                        "{%0,%1,%2,%3}, {%4,%5,%6,%7}, {%8,%9}, {%0,%1,%2,%3};"
                        : "+f"(acc[i][j][0]), "+f"(acc[i][j][1]),
                          "+f"(acc[i][j][2]), "+f"(acc[i][j][3])
                        : "r"(af[cur][i][0]), "r"(af[cur][i][1]),
                          "r"(af[cur][i][2]), "r"(af[cur][i][3]),
                          "r"(bf[cur][j][0]), "r"(bf[cur][j][1]));
                }
        }
    }
    #pragma unroll
    for (int i=0;i<4;i++){
        int r0 = bm0 + wm*64 + i*16 + gid;
        #pragma unroll
        for (int j=0;j<4;j++){
            int cc = bn0 + wn*32 + j*8 + qid*2;
            float2 v0, v1;
            v0.x = acc[i][j][0]; v0.y = acc[i][j][1];
            v1.x = acc[i][j][2]; v1.y = acc[i][j][3];
            *(float2*)(g_gemm + (size_t) r0   *DIMF + cc) = v0;
            *(float2*)(g_gemm + (size_t)(r0+8)*DIMF + cc) = v1;
        }
    }
}

// ---------------- hid GEMM (small; register-staged path) ----------------
template<int BM,int BN,int BK,int WM,int WN,bool BIAS>
__device__ __forceinline__ void mma_body(
        const float* __restrict__ A, const float* __restrict__ B,
        float* __restrict__ C, int N, int K,
        float alpha, const float* __restrict__ bias,
        unsigned* As, unsigned* Bs){
    constexpr int MT = WM/16, NT = WN/8, KT = BK/8;
    constexpr int WARPS_N = BN/WN;
    constexpr int PA = BK+4;
    constexpr int PB = BN+8;
    constexpr int AREG = BM*BK/1024;
    constexpr int BREG = BK*BN/1024;

    const int tid = threadIdx.x;
    const int warp = tid>>5, lane = tid&31;
    const int wm = warp / WARPS_N, wn = warp % WARPS_N;
    const int gid = lane>>2, qid = lane&3;
    const int bm0 = blockIdx.y*BM, bn0 = blockIdx.x*BN;

    float4 ra[AREG], rb[BREG];

    auto ldg_tile = [&](int k0){
        #pragma unroll
        for (int a=0;a<AREG;a++){
            int i = tid*4 + a*1024;
            int r = i/BK, c = i%BK;
            ra[a] = *(const float4*)(A + (size_t)(bm0+r)*K + k0 + c);
        }
        #pragma unroll
        for (int b=0;b<BREG;b++){
            int i = tid*4 + b*1024;
            int r = i/BN, c = i%BN;
            rb[b] = *(const float4*)(B + (size_t)(k0+r)*N + bn0 + c);
        }
    };
    auto sts_tile = [&](){
        #pragma unroll
        for (int a=0;a<AREG;a++){
            int i = tid*4 + a*1024;
            int r = i/BK, c = i%BK;
            uint4 p;
            p.x=f2tf32(ra[a].x); p.y=f2tf32(ra[a].y);
            p.z=f2tf32(ra[a].z); p.w=f2tf32(ra[a].w);
            *(uint4*)&As[r*PA+c] = p;
        }
        #pragma unroll
        for (int b=0;b<BREG;b++){
            int i = tid*4 + b*1024;
            int r = i/BN, c = i%BN;
            uint4 p;
            p.x=f2tf32(rb[b].x); p.y=f2tf32(rb[b].y);
            p.z=f2tf32(rb[b].z); p.w=f2tf32(rb[b].w);
            *(uint4*)&Bs[r*PB+c] = p;
        }
    };

    float acc[MT][NT][4];
    #pragma unroll
    for (int i=0;i<MT;i++)
        #pragma unroll
        for (int j=0;j<NT;j++)
            #pragma unroll
            for (int q=0;q<4;q++) acc[i][j][q]=0.f;

    ldg_tile(0);
    sts_tile();
    __syncthreads();

    const int NIT = K/BK;
    for (int it=0; it<NIT; it++){
        if (it+1 < NIT) ldg_tile((it+1)*BK);
        #pragma unroll
        for (int kk=0; kk<KT; kk++){
            unsigned af[MT][4], bf[NT][2];
            #pragma unroll
            for (int i=0;i<MT;i++){
                int r0 = wm*WM + i*16 + gid;
                int c0 = kk*8 + qid;
                af[i][0]=As[ r0   *PA + c0  ];
                af[i][1]=As[(r0+8)*PA + c0  ];
                af[i][2]=As[ r0   *PA + c0+4];
                af[i][3]=As[(r0+8)*PA + c0+4];
            }
            #pragma unroll
            for (int j=0;j<NT;j++){
                int cc = wn*WN + j*8 + gid;
                bf[j][0]=Bs[(kk*8+qid  )*PB + cc];
                bf[j][1]=Bs[(kk*8+qid+4)*PB + cc];
            }
            #pragma unroll
            for (int i=0;i<MT;i++)
                #pragma unroll
                for (int j=0;j<NT;j++){
                    asm volatile(
                        "mma.sync.aligned.m16n8k8.row.col.f32.tf32.tf32.f32 "
                        "{%0,%1,%2,%3}, {%4,%5,%6,%7}, {%8,%9}, {%0,%1,%2,%3};"
                        : "+f"(acc[i][j][0]), "+f"(acc[i][j][1]),
                          "+f"(acc[i][j][2]), "+f"(acc[i][j][3])
                        : "r"(af[i][0]), "r"(af[i][1]), "r"(af[i][2]), "r"(af[i][3]),
                          "r"(bf[j][0]), "r"(bf[j][1]));
                }
        }
        __syncthreads();
        if (it+1 < NIT){
            sts_tile();
            __syncthreads();
        }
    }
    #pragma unroll
    for (int i=0;i<MT;i++){
        int r0 = bm0 + wm*WM + i*16 + gid;
        #pragma unroll
        for (int j=0;j<NT;j++){
            int cc = bn0 + wn*WN + j*8 + qid*2;
            float b0 = BIAS ? bias[cc] : 0.f;
            float b1 = BIAS ? bias[cc+1] : 0.f;
            float2 v0, v1;
            v0.x = alpha*acc[i][j][0] + b0;
            v0.y = alpha*acc[i][j][1] + b1;
            v1.x = alpha*acc[i][j][2] + b0;
            v1.y = alpha*acc[i][j][3] + b1;
            *(float2*)(C + (size_t) r0   *N + cc) = v0;
            *(float2*)(C + (size_t)(r0+8)*N + cc) = v1;
        }
    }
}

#define HID_SMEM ((64*36 + 32*72)*4)
__global__ void __launch_bounds__(256) mma_hid_kernel(const float* __restrict__ Bw,
                                                      const float* __restrict__ bias){
    extern __shared__ unsigned dyn[];
    unsigned* As = dyn;
    unsigned* Bs = dyn + 64*36;
    mma_body<64,64,32,16,32,true>(g_acc, Bw, g_nf, HID, DIMF,
                                  0.2f, bias, As, Bs);
}

// ---------------- per layer: LN + leaky + feat/acc update + next su ----------------
__global__ void ln_su_kernel(const float* __restrict__ linb,
                             const float* __restrict__ lng,
                             const float* __restrict__ lnb,
                             const float* __restrict__ a1next){
    int n = blockIdx.x, tid = threadIdx.x;
    float4 x = ((const float4*)g_gemm)[(size_t)n*256+tid];
    float4 bb = ((const float4*)linb)[tid];
    x.x+=bb.x; x.y+=bb.y; x.z+=bb.z; x.w+=bb.w;
    __shared__ float sm[32];
    float s = x.x+x.y+x.z+x.w;
    s = block_reduce_256(s, sm);
    float mu = s*(1.f/1024.f);
    float d0=x.x-mu, d1=x.y-mu, d2=x.z-mu, d3=x.w-mu;
    float q = d0*d0+d1*d1+d2*d2+d3*d3;
    q = block_reduce_256(q, sm);
    float r = rsqrtf(q*(1.f/1024.f)+EPSV);
    float4 gg = ((const float4*)lng)[tid];
    float4 b2 = ((const float4*)lnb)[tid];
    float4 y;
    y.x = lk(gg.x*d0*r + b2.x);
    y.y = lk(gg.y*d1*r + b2.y);
    y.z = lk(gg.z*d2*r + b2.z);
    y.w = lk(gg.w*d3*r + b2.w);
    ((float4*)g_feat)[(size_t)n*256+tid] = y;
    float4 a = ((float4*)g_acc)[(size_t)n*256+tid];
    a.x+=y.x; a.y+=y.y; a.z+=y.z; a.w+=y.w;
    ((float4*)g_acc)[(size_t)n*256+tid] = a;
    if (a1next){
        float4 av = ((const float4*)a1next)[tid];
        float p = y.x*av.x + y.y*av.y + y.z*av.z + y.w*av.w;
        p = block_reduce_256(p, sm);
        if (tid==0) g_su[n]=p;
    }
}

// ---------------- surface path ----------------
__global__ void surf_lin_kernel(const float* __restrict__ sf,
                                const float* __restrict__ W,
                                const float* __restrict__ b){
    int c  = threadIdx.x & 63;
    int ry = threadIdx.x >> 6;
    int row0 = blockIdx.x * 64;
    float w0=W[c], w1=W[64+c], w2=W[128+c], bc=b[c];
    float ls=0.f, lss=0.f;
    for (int r=ry; r<64; r+=4){
        int row = row0 + r;
        float x0=sf[row*3], x1=sf[row*3+1], x2=sf[row*3+2];
        float y = fmaf(x0,w0, fmaf(x1,w1, fmaf(x2,w2, bc)));
        g_surfy[row*64+c]=y; ls+=y; lss+=y*y;
    }
    __shared__ float ss[256], sq[256];
    ss[threadIdx.x]=ls; sq[threadIdx.x]=lss;
    __syncthreads();
    if (ry==0){
        float t  = ss[c]+ss[64+c]+ss[128+c]+ss[192+c];
        float t2 = sq[c]+sq[64+c]+sq[128+c]+sq[192+c];
        atomicAdd(&g_stats[c], t);
        atomicAdd(&g_stats[64+c], t2);
    }
}

__global__ void finalize_stats_kernel(int which, float n){
    float* st = which ? g_stats2 : g_stats;
    int c = threadIdx.x;
    float mu  = st[c] / n;
    float var = st[64+c]/n - mu*mu;
    st[c]   = mu;
    st[64+c]= rsqrtf(fmaxf(var,0.f)+EPSV);
}

__global__ void surf_norm_scatter_kernel(const int* __restrict__ surf_res,
                                         const float* __restrict__ g,
                                         const float* __restrict__ beta){
    int idx = blockIdx.x*256 + threadIdx.x;
    int row = idx >> 6, c = idx & 63;
    float y = g_surfy[idx];
    float v = lk(g[c]*(y - g_stats[c])*g_stats[64+c] + beta[c]);
    int t = surf_res[row];
    atomicAdd(&g_ressum[t*64 + c], v);
    if (c==0) atomicAdd(&g_rescnt[t], 1.f);
}

// ---------------- final heads ----------------
__global__ void prot_kernel(const float* __restrict__ g,
                            const float* __restrict__ b,
                            float* __restrict__ out){
    int gr = blockIdx.x, c = threadIdx.x;
    const float* base = g_nf + (size_t)gr*512*64;
    float s = 0.f;
    for (int r=0;r<512;r++) s += base[r*64+c];
    float x = s*(1.f/512.f);
    __shared__ float sm[64];
    __shared__ float s_mu, s_r;
    sm[c]=x; __syncthreads();
    if (c==0){ float t=0.f; for (int i=0;i<64;i++) t+=sm[i]; s_mu=t*(1.f/64.f); }
    __syncthreads();
    float d = x - s_mu;
    sm[c]=d*d; __syncthreads();
    if (c==0){ float t=0.f; for (int i=0;i<64;i++) t+=sm[i]; s_r=rsqrtf(t*(1.f/64.f)+EPSV); }
    __syncthreads();
    out[gr*64+c] = lk(g[c]*d*s_r + b[c]);
}

// ns_a now gathers surface means directly from g_ressum/g_rescnt (gather_s fused away)
__global__ void ns_a_kernel(const int* __restrict__ uniq,
                            const float* __restrict__ dw,
                            const float* __restrict__ db){
    __shared__ float s_wd[128*64];
    __shared__ float z_s[128];
    int tid = threadIdx.x;
    for (int i=tid; i<128*64; i+=64) s_wd[i]=dw[i];
    float bc = db[tid];
    float ls=0.f, lss=0.f;
    __syncthreads();
    int row0 = blockIdx.x*64;
    for (int r=0;r<64;r++){
        int row = row0 + r;
        if (row >= NUNIQ) break;
        int u = uniq[row];
        z_s[tid]    = g_nf[(size_t)u*64 + tid];
        z_s[64+tid] = g_ressum[(size_t)u*64 + tid] / fmaxf(g_rescnt[u], 1.f);
        __syncthreads();
        float y = bc;
        #pragma unroll 8
        for (int k=0;k<128;k++) y = fmaf(z_s[k], s_wd[k*64+tid], y);
        g_y2[(size_t)row*64+tid] = y;
        ls += y; lss += y*y;
        __syncthreads();
    }
    atomicAdd(&g_stats2[tid], ls);
    atomicAdd(&g_stats2[64+tid], lss);
}

__global__ void ns_norm_scatter_kernel(const int* __restrict__ res_batch,
                                       const float* __restrict__ g,
                                       const float* __restrict__ beta){
    int idx = blockIdx.x*256 + threadIdx.x;
    int row = idx >> 6, c = idx & 63;
    float y = g_y2[idx];
    float v = lk(g[c]*(y - g_stats2[c])*g_stats2[64+c] + beta[c]);
    int t = res_batch[row];
    atomicAdd(&g_nssum[t*64 + c], v);
    if (c==0) atomicAdd(&g_nscnt[t], 1.f);
}

__global__ void ns_final_kernel(const float* __restrict__ bng,
                                const float* __restrict__ bnb,
                                float* __restrict__ out){
    int tid = threadIdx.x;
    int gr = tid >> 6, c = tid & 63;
    float v = g_nssum[tid] / fmaxf(g_nscnt[gr], 1.f);
    __shared__ float sm[1024];
    __shared__ float s_mu[64], s_r[64];
    sm[tid]=v; __syncthreads();
    if (gr==0){
        float t=0.f, t2=0.f;
        for (int r=0;r<16;r++){ float x=sm[r*64+c]; t+=x; t2+=x*x; }
        float mu = t*(1.f/16.f);
        s_mu[c]=mu;
        s_r[c]=rsqrtf(fmaxf(t2*(1.f/16.f)-mu*mu,0.f)+EPSV);
    }
    __syncthreads();
    out[16*64 + tid] = lk(bng[c]*(v - s_mu[c])*s_r[c] + bnb[c]);
}

// ---------------- host ----------------
extern "C" void kernel_launch(void* const* d_in, const int* in_sizes, int n_in,
                              void* d_out, int out_size){
    const int*   ei         = (const int*)  d_in[0];
    const float* n_feats    = (const float*)d_in[1];
    const float* surf_feats = (const float*)d_in[3];
    const int*   surf_res   = (const int*)  d_in[4];
    const int*   res_batch  = (const int*)  d_in[5];
    const int*   uniq       = (const int*)  d_in[6];
    const float* surf_up_w  = (const float*)d_in[7];
    const float* surf_up_b  = (const float*)d_in[8];
    const float* surf_up_g  = (const float*)d_in[9];
    const float* surf_up_be = (const float*)d_in[10];
    const float* a_w        = (const float*)d_in[11];
    const float* lin_w      = (const float*)d_in[12];
    const float* lin_b      = (const float*)d_in[13];
    const float* ln_g       = (const float*)d_in[14];
    const float* ln_b       = (const float*)d_in[15];
    const float* hid_w      = (const float*)d_in[16];
    const float* hid_b      = (const float*)d_in[17];
    const float* down_w     = (const float*)d_in[18];
    const float* down_b     = (const float*)d_in[19];
    const float* down_g     = (const float*)d_in[20];
    const float* down_be    = (const float*)d_in[21];
    const float* prot_ln_g  = (const float*)d_in[22];
    const float* prot_ln_b  = (const float*)d_in[23];
    const float* surf_bn_g  = (const float*)d_in[24];
    const float* surf_bn_b  = (const float*)d_in[25];
    float* out = (float*)d_out;

    cudaFuncSetAttribute(mma_main_kernel,
                         cudaFuncAttributeMaxDynamicSharedMemorySize, MAIN_SMEM);
    cudaFuncSetAttribute(mma_hid_kernel,
                         cudaFuncAttributeMaxDynamicSharedMemorySize, HID_SMEM);

    zero_kernel<<<(NNODES*HID)/256, 256>>>();                       // 1
    degfill_kernel<<<1, 1024>>>(ei);                                // 2
    init_su_kernel<<<NNODES, 256>>>(n_feats, a_w, lin_w);           // 3

    for (int l=0; l<4; l++){
        smagg_kernel<<<NNODES, 256>>>();                            // 4 <- profiled (l=0)
        mma_main_kernel<<<dim3(DIMF/128, NNODES/128), 256, MAIN_SMEM>>>(l);
        const float* a1n = (l<3) ? (a_w + (size_t)(l+1)*2*DIMF) : nullptr;
        ln_su_kernel<<<NNODES, 256>>>(lin_b + (size_t)l*DIMF,
                                      ln_g + (size_t)l*DIMF,
                                      ln_b + (size_t)l*DIMF, a1n);
    }

    mma_hid_kernel<<<dim3(1, NNODES/64), 256, HID_SMEM>>>(hid_w, hid_b);
    prot_kernel<<<NGRAPH, 64>>>(prot_ln_g, prot_ln_b, out);

    surf_lin_kernel<<<NSURF/64, 256>>>(surf_feats, surf_up_w, surf_up_b);
    finalize_stats_kernel<<<1,64>>>(0, (float)NSURF);
    surf_norm_scatter_kernel<<<(NSURF*HID)/256, 256>>>(surf_res, surf_up_g, surf_up_be);

    ns_a_kernel<<<(NUNIQ+63)/64, 64>>>(uniq, down_w, down_b);
    finalize_stats_kernel<<<1,64>>>(1, (float)NUNIQ);
    ns_norm_scatter_kernel<<<(NUNIQ*HID)/256, 256>>>(res_batch, down_g, down_be);
    ns_final_kernel<<<1,1024>>>(surf_bn_g, surf_bn_b, out);
}

// round 13
// speedup vs baseline: 1.3584x; 1.3166x over previous
#include <cuda_runtime.h>
#include <cuda_fp16.h>
#include <cstdint>
#include <math.h>

#define NNODES 8192
#define NEDGES 65536
#define NSURF  40000
#define NUNIQ  6000
#define NGRAPH 16
#define DIMF   1024
#define HID    64
#define EPSV   1e-5f
#define SLOPE  0.01f

// ---------------- scratch (device globals; referenced ONLY in device code) ----------------
__device__ float    g_feat[NNODES*DIMF];
__device__ float    g_acc [NNODES*DIMF];
__device__ __half   g_aggh[NNODES*DIMF];         // fp16 A operand, row-major [m][k]
__device__ __half2  g_bwh [4*512*1024];          // fp16 B weights, [layer][k/2][n] pair-interleaved
__device__ float    g_gemm[NNODES*DIMF];
__device__ float    g_surfy[NSURF*HID];
__device__ float    g_ressum[NNODES*HID];
__device__ float    g_rescnt[NNODES];
__device__ float    g_su[NNODES];
__device__ int      g_csru[NEDGES];
__device__ int      g_rowptr[NNODES+1];
__device__ float    g_stats [2*HID];
__device__ float    g_stats2[2*HID];
__device__ float    g_nf[NNODES*HID];
__device__ float    g_y2[NUNIQ*HID];
__device__ float    g_nssum[NGRAPH*HID];
__device__ float    g_nscnt[NGRAPH];

__device__ __forceinline__ float lk(float x){ return x >= 0.f ? x : SLOPE*x; }

__device__ __forceinline__ unsigned f2tf32(float f){
    unsigned r;
    asm("cvt.rna.tf32.f32 %0, %1;" : "=r"(r) : "f"(f));
    return r;
}

__device__ __forceinline__ float block_reduce_256(float v, float* sm){
    #pragma unroll
    for (int o=16;o>0;o>>=1) v += __shfl_xor_sync(0xffffffffu, v, o);
    int warp = threadIdx.x>>5, lane = threadIdx.x&31;
    if (lane==0) sm[warp]=v;
    __syncthreads();
    if (warp==0){
        v = (lane<8)? sm[lane] : 0.f;
        #pragma unroll
        for (int o=4;o>0;o>>=1) v += __shfl_xor_sync(0xffffffffu, v, o);
        if (lane==0) sm[0]=v;
    }
    __syncthreads();
    float r = sm[0];
    __syncthreads();
    return r;
}

__device__ __forceinline__ float block_reduce_max_256(float v, float* sm){
    #pragma unroll
    for (int o=16;o>0;o>>=1) v = fmaxf(v, __shfl_xor_sync(0xffffffffu, v, o));
    int warp = threadIdx.x>>5, lane = threadIdx.x&31;
    if (lane==0) sm[warp]=v;
    __syncthreads();
    if (warp==0){
        v = (lane<8)? sm[lane] : -1e30f;
        #pragma unroll
        for (int o=4;o>0;o>>=1) v = fmaxf(v, __shfl_xor_sync(0xffffffffu, v, o));
        if (lane==0) sm[0]=v;
    }
    __syncthreads();
    float r = sm[0];
    __syncthreads();
    return r;
}

// ---------------- launch 1: zeroing ----------------
__global__ void zero_kernel(){
    int i = blockIdx.x*256 + threadIdx.x;
    if (i < NNODES*HID) g_ressum[i] = 0.f;
    if (i < NNODES) g_rescnt[i]=0.f;
    if (i < 2*HID){ g_stats[i]=0.f; g_stats2[i]=0.f; }
    if (i < NGRAPH*HID) g_nssum[i]=0.f;
    if (i < NGRAPH) g_nscnt[i]=0.f;
}

// ---------------- launch 2: fused degree histogram + scan + CSR fill ----------------
__global__ void degfill_kernel(const int* __restrict__ ei){
    __shared__ int cnt[NNODES];
    __shared__ int sm[1024];
    int tid = threadIdx.x;
    for (int i=tid; i<NNODES; i+=1024) cnt[i]=0;
    __syncthreads();
    for (int e=tid; e<NEDGES; e+=1024) atomicAdd(&cnt[ei[NEDGES+e]], 1);
    __syncthreads();
    int base = tid*8;
    int loc[8]; int s=0;
    #pragma unroll
    for (int j=0;j<8;j++){ loc[j]=s; s += cnt[base+j]; }
    sm[tid]=s; __syncthreads();
    for (int off=1; off<1024; off<<=1){
        int t = (tid>=off) ? sm[tid-off] : 0;
        __syncthreads();
        sm[tid]+=t;
        __syncthreads();
    }
    int excl = sm[tid]-s;
    int st[8];
    #pragma unroll
    for (int j=0;j<8;j++){ st[j] = excl + loc[j]; g_rowptr[base+j] = st[j]; }
    if (tid==1023) g_rowptr[NNODES] = sm[1023];
    __syncthreads();
    #pragma unroll
    for (int j=0;j<8;j++) cnt[base+j] = st[j];
    __syncthreads();
    for (int e=tid; e<NEDGES; e+=1024){
        int v = ei[NEDGES+e];
        int p = atomicAdd(&cnt[v], 1);
        g_csru[p] = ei[e];
    }
}

// ---------------- launch 3: init copy + su(layer0) + weight->fp16 pair conversion ----------------
__global__ void init_su_kernel(const float* __restrict__ nf,
                               const float* __restrict__ a1,
                               const float* __restrict__ lw){
    int n = blockIdx.x, tid = threadIdx.x;
    float4 v = ((const float4*)nf)[(size_t)n*256+tid];
    ((float4*)g_feat)[(size_t)n*256+tid]=v;
    ((float4*)g_acc)[(size_t)n*256+tid]=v;
    // weight conversion: flat idx over [4][512][1024] half2 outputs (exactly 2M threads)
    {
        size_t idx = (size_t)n*256 + tid;
        int l   = (int)(idx >> 19);
        int rem = (int)(idx & 524287);
        int k2  = rem >> 10;
        int nn  = rem & 1023;
        const float* base = lw + ((size_t)l << 20);
        float v0 = base[(size_t)(2*k2  )*1024 + nn];
        float v1 = base[(size_t)(2*k2+1)*1024 + nn];
        g_bwh[idx] = __floats2half2_rn(v0, v1);
    }
    float4 a = ((const float4*)a1)[tid];
    float p = v.x*a.x + v.y*a.y + v.z*a.z + v.w*a.w;
    __shared__ float sm[32];
    p = block_reduce_256(p, sm);
    if (tid==0) g_su[n]=p;
}

// ---------------- launch 4: fused edge-softmax + aggregate; stores fp16 A ----------------
__global__ void smagg_kernel(){
    int n = blockIdx.x, tid = threadIdx.x;
    int s = g_rowptr[n], e = g_rowptr[n+1];
    __shared__ float s_w[256]; __shared__ int s_u[256];
    __shared__ float red[32];
    float m = -1e30f;
    for (int j=s+tid; j<e; j+=256) m = fmaxf(m, g_su[g_csru[j]]);
    m = block_reduce_max_256(m, red);
    float lsum = 0.f;
    float4 acc = make_float4(0.f,0.f,0.f,0.f);
    const float4* F4 = (const float4*)g_feat;
    for (int base=s; base<e; base+=256){
        int j = base + tid;
        if (j<e){
            int u = g_csru[j];
            float ex = __expf(g_su[u] - m);
            s_w[tid]=ex; s_u[tid]=u; lsum += ex;
        }
        __syncthreads();
        int cnt = min(256, e-base);
        for (int t=0;t<cnt;t++){
            float wv = s_w[t]; int u = s_u[t];
            float4 f = F4[(size_t)u*256 + tid];
            acc.x += wv*f.x; acc.y += wv*f.y; acc.z += wv*f.z; acc.w += wv*f.w;
        }
        __syncthreads();
    }
    float total = block_reduce_256(lsum, red);
    if (total > 0.f){
        float inv = 1.f/total;
        acc.x*=inv; acc.y*=inv; acc.z*=inv; acc.w*=inv;
    }
    __half2 h0 = __floats2half2_rn(acc.x, acc.y);
    __half2 h1 = __floats2half2_rn(acc.z, acc.w);
    __half2* dst = (__half2*)(g_aggh + (size_t)n*DIMF + tid*4);
    dst[0]=h0; dst[1]=h1;
}

// ---------------- launch 5: main fp16 GEMM (mma.sync m16n8k16) ----------------
// BM=128, BN=128, BK=32 halves (2 k16-steps). 256 thr, 2 blk/SM, 3-stage cp.async.
#define STG  3
#define PA2  20                   // A smem pitch in half2/uns (16 + pad 4)
#define PB2  136                  // B smem pitch in half2/uns (128 + pad 8)
#define ASZ2 (128*PA2)
#define BSZ2 (16*PB2)
#define MAIN_SMEM (STG*(ASZ2+BSZ2)*4)

__global__ void __launch_bounds__(256,2) mma_main_kernel(int layer){
    extern __shared__ unsigned dyn[];
    unsigned* AsB = dyn;
    unsigned* BsB = dyn + STG*ASZ2;
    const __half*  A = g_aggh;
    const unsigned* B = (const unsigned*)(g_bwh + (size_t)layer*524288);

    const int tid = threadIdx.x;
    const int warp = tid>>5, lane = tid&31;
    const int wm = warp>>2, wn = warp&3;         // 2x4 warps, warp tile 64x32
    const int gid = lane>>2, qid = lane&3;
    const int bm0 = blockIdx.y*128, bn0 = blockIdx.x*128;

    // cp.async mapping: A 512 chunks of 16B (128 rows x 4), B 512 chunks (16 rows x 32)
    const int ar = tid>>1,        ac = (tid&1)*8;    // A: row, half-offset (16B = 8 halves)
    const int br = tid>>4,        bc = (tid&15)*8;   // B: k2-row (0..15), un-offset/2? cols in uns

    auto issue = [&](int it){
        unsigned* As = AsB + (it%STG)*ASZ2;
        unsigned* Bs = BsB + (it%STG)*BSZ2;
        int k0 = it*32;       // halves
        int k20 = it*16;      // half2 rows in B
        #pragma unroll
        for (int a=0;a<2;a++){
            int r = ar + a*128;      // rows 0..255? no: 2 chunks/thread over 512 => rows 0..127 twice
            // chunks: chunk = tid + a*256; row = chunk>>2; c16 = chunk&3
            int chunk = tid + a*256;
            int row = chunk>>2, c16 = chunk&3;
            unsigned dst = (unsigned)__cvta_generic_to_shared(&As[row*PA2 + c16*4]);
            asm volatile("cp.async.cg.shared.global [%0], [%1], 16;"
                         :: "r"(dst), "l"(A + (size_t)(bm0+row)*DIMF + k0 + c16*8));
        }
        #pragma unroll
        for (int b=0;b<2;b++){
            int chunk = tid + b*256;
            int row = chunk>>5, c4 = chunk&31;   // 16 rows x 32 chunks (128 uns/row)
            unsigned dst = (unsigned)__cvta_generic_to_shared(&Bs[row*PB2 + c4*4]);
            asm volatile("cp.async.cg.shared.global [%0], [%1], 16;"
                         :: "r"(dst), "l"(B + (size_t)(k20+row)*1024 + bn0 + c4*4));
        }
        asm volatile("cp.async.commit_group;" ::: "memory");
    };
    (void)ar; (void)ac; (void)br; (void)bc;

    float acc[4][4][4];
    #pragma unroll
    for (int i=0;i<4;i++)
        #pragma unroll
        for (int j=0;j<4;j++)
            #pragma unroll
            for (int q=0;q<4;q++) acc[i][j][q]=0.f;

    issue(0); issue(1);

    const int NIT = DIMF/32;
    for (int it=0; it<NIT; it++){
        asm volatile("cp.async.wait_group 1;" ::: "memory");
        __syncthreads();
        if (it+2 < NIT) issue(it+2);
        const unsigned* curA = AsB + (it%STG)*ASZ2;
        const unsigned* curB = BsB + (it%STG)*BSZ2;
        #pragma unroll
        for (int kk=0; kk<2; kk++){
            unsigned af[4][4], bf[4][2];
            #pragma unroll
            for (int i=0;i<4;i++){
                int r0 = wm*64 + i*16 + gid;
                int c0 = kk*8 + qid;
                af[i][0]=curA[ r0   *PA2 + c0  ];
                af[i][1]=curA[(r0+8)*PA2 + c0  ];
                af[i][2]=curA[ r0   *PA2 + c0+4];
                af[i][3]=curA[(r0+8)*PA2 + c0+4];
            }
            #pragma unroll
            for (int j=0;j<4;j++){
                int cc = wn*32 + j*8 + gid;
                bf[j][0]=curB[(kk*8+qid  )*PB2 + cc];
                bf[j][1]=curB[(kk*8+qid+4)*PB2 + cc];
            }
            #pragma unroll
            for (int i=0;i<4;i++)
                #pragma unroll
                for (int j=0;j<4;j++){
                    asm volatile(
                        "mma.sync.aligned.m16n8k16.row.col.f32.f16.f16.f32 "
                        "{%0,%1,%2,%3}, {%4,%5,%6,%7}, {%8,%9}, {%0,%1,%2,%3};"
                        : "+f"(acc[i][j][0]), "+f"(acc[i][j][1]),
                          "+f"(acc[i][j][2]), "+f"(acc[i][j][3])
                        : "r"(af[i][0]), "r"(af[i][1]), "r"(af[i][2]), "r"(af[i][3]),
                          "r"(bf[j][0]), "r"(bf[j][1]));
                }
        }
    }
    #pragma unroll
    for (int i=0;i<4;i++){
        int r0 = bm0 + wm*64 + i*16 + gid;
        #pragma unroll
        for (int j=0;j<4;j++){
            int cc = bn0 + wn*32 + j*8 + qid*2;
            float2 v0, v1;
            v0.x = acc[i][j][0]; v0.y = acc[i][j][1];
            v1.x = acc[i][j][2]; v1.y = acc[i][j][3];
            *(float2*)(g_gemm + (size_t) r0   *DIMF + cc) = v0;
            *(float2*)(g_gemm + (size_t)(r0+8)*DIMF + cc) = v1;
        }
    }
}

// ---------------- hid GEMM (small; tf32 register-staged path, unchanged) ----------------
template<int BM,int BN,int BK,int WM,int WN,bool BIAS>
__device__ __forceinline__ void mma_body(
        const float* __restrict__ A, const float* __restrict__ B,
        float* __restrict__ C, int N, int K,
        float alpha, const float* __restrict__ bias,
        unsigned* As, unsigned* Bs){
    constexpr int MT = WM/16, NT = WN/8, KT = BK/8;
    constexpr int WARPS_N = BN/WN;
    constexpr int PA = BK+4;
    constexpr int PB = BN+8;
    constexpr int AREG = BM*BK/1024;
    constexpr int BREG = BK*BN/1024;

    const int tid = threadIdx.x;
    const int warp = tid>>5, lane = tid&31;
    const int wm = warp / WARPS_N, wn = warp % WARPS_N;
    const int gid = lane>>2, qid = lane&3;
    const int bm0 = blockIdx.y*BM, bn0 = blockIdx.x*BN;

    float4 ra[AREG], rb[BREG];

    auto ldg_tile = [&](int k0){
        #pragma unroll
        for (int a=0;a<AREG;a++){
            int i = tid*4 + a*1024;
            int r = i/BK, c = i%BK;
            ra[a] = *(const float4*)(A + (size_t)(bm0+r)*K + k0 + c);
        }
        #pragma unroll
        for (int b=0;b<BREG;b++){
            int i = tid*4 + b*1024;
            int r = i/BN, c = i%BN;
            rb[b] = *(const float4*)(B + (size_t)(k0+r)*N + bn0 + c);
        }
    };
    auto sts_tile = [&](){
        #pragma unroll
        for (int a=0;a<AREG;a++){
            int i = tid*4 + a*1024;
            int r = i/BK, c = i%BK;
            uint4 p;
            p.x=f2tf32(ra[a].x); p.y=f2tf32(ra[a].y);
            p.z=f2tf32(ra[a].z); p.w=f2tf32(ra[a].w);
            *(uint4*)&As[r*PA+c] = p;
        }
        #pragma unroll
        for (int b=0;b<BREG;b++){
            int i = tid*4 + b*1024;
            int r = i/BN, c = i%BN;
            uint4 p;
            p.x=f2tf32(rb[b].x); p.y=f2tf32(rb[b].y);
            p.z=f2tf32(rb[b].z); p.w=f2tf32(rb[b].w);
            *(uint4*)&Bs[r*PB+c] = p;
        }
    };

    float acc[MT][NT][4];
    #pragma unroll
    for (int i=0;i<MT;i++)
        #pragma unroll
        for (int j=0;j<NT;j++)
            #pragma unroll
            for (int q=0;q<4;q++) acc[i][j][q]=0.f;

    ldg_tile(0);
    sts_tile();
    __syncthreads();

    const int NIT = K/BK;
    for (int it=0; it<NIT; it++){
        if (it+1 < NIT) ldg_tile((it+1)*BK);
        #pragma unroll
        for (int kk=0; kk<KT; kk++){
            unsigned af[MT][4], bf[NT][2];
            #pragma unroll
            for (int i=0;i<MT;i++){
                int r0 = wm*WM + i*16 + gid;
                int c0 = kk*8 + qid;
                af[i][0]=As[ r0   *PA + c0  ];
                af[i][1]=As[(r0+8)*PA + c0  ];
                af[i][2]=As[ r0   *PA + c0+4];
                af[i][3]=As[(r0+8)*PA + c0+4];
            }
            #pragma unroll
            for (int j=0;j<NT;j++){
                int cc = wn*WN + j*8 + gid;
                bf[j][0]=Bs[(kk*8+qid  )*PB + cc];
                bf[j][1]=Bs[(kk*8+qid+4)*PB + cc];
            }
            #pragma unroll
            for (int i=0;i<MT;i++)
                #pragma unroll
                for (int j=0;j<NT;j++){
                    asm volatile(
                        "mma.sync.aligned.m16n8k8.row.col.f32.tf32.tf32.f32 "
                        "{%0,%1,%2,%3}, {%4,%5,%6,%7}, {%8,%9}, {%0,%1,%2,%3};"
                        : "+f"(acc[i][j][0]), "+f"(acc[i][j][1]),
                          "+f"(acc[i][j][2]), "+f"(acc[i][j][3])
                        : "r"(af[i][0]), "r"(af[i][1]), "r"(af[i][2]), "r"(af[i][3]),
                          "r"(bf[j][0]), "r"(bf[j][1]));
                }
        }
        __syncthreads();
        if (it+1 < NIT){
            sts_tile();
            __syncthreads();
        }
    }
    #pragma unroll
    for (int i=0;i<MT;i++){
        int r0 = bm0 + wm*WM + i*16 + gid;
        #pragma unroll
        for (int j=0;j<NT;j++){
            int cc = bn0 + wn*WN + j*8 + qid*2;
            float b0 = BIAS ? bias[cc] : 0.f;
            float b1 = BIAS ? bias[cc+1] : 0.f;
            float2 v0, v1;
            v0.x = alpha*acc[i][j][0] + b0;
            v0.y = alpha*acc[i][j][1] + b1;
            v1.x = alpha*acc[i][j][2] + b0;
            v1.y = alpha*acc[i][j][3] + b1;
            *(float2*)(C + (size_t) r0   *N + cc) = v0;
            *(float2*)(C + (size_t)(r0+8)*N + cc) = v1;
        }
    }
}

#define HID_SMEM ((64*36 + 32*72)*4)
__global__ void __launch_bounds__(256) mma_hid_kernel(const float* __restrict__ Bw,
                                                      const float* __restrict__ bias){
    extern __shared__ unsigned dyn[];
    unsigned* As = dyn;
    unsigned* Bs = dyn + 64*36;
    mma_body<64,64,32,16,32,true>(g_acc, Bw, g_nf, HID, DIMF,
                                  0.2f, bias, As, Bs);
}

// ---------------- per layer: LN + leaky + feat/acc update + next su ----------------
__global__ void ln_su_kernel(const float* __restrict__ linb,
                             const float* __restrict__ lng,
                             const float* __restrict__ lnb,
                             const float* __restrict__ a1next){
    int n = blockIdx.x, tid = threadIdx.x;
    float4 x = ((const float4*)g_gemm)[(size_t)n*256+tid];
    float4 bb = ((const float4*)linb)[tid];
    x.x+=bb.x; x.y+=bb.y; x.z+=bb.z; x.w+=bb.w;
    __shared__ float sm[32];
    float s = x.x+x.y+x.z+x.w;
    s = block_reduce_256(s, sm);
    float mu = s*(1.f/1024.f);
    float d0=x.x-mu, d1=x.y-mu, d2=x.z-mu, d3=x.w-mu;
    float q = d0*d0+d1*d1+d2*d2+d3*d3;
    q = block_reduce_256(q, sm);
    float r = rsqrtf(q*(1.f/1024.f)+EPSV);
    float4 gg = ((const float4*)lng)[tid];
    float4 b2 = ((const float4*)lnb)[tid];
    float4 y;
    y.x = lk(gg.x*d0*r + b2.x);
    y.y = lk(gg.y*d1*r + b2.y);
    y.z = lk(gg.z*d2*r + b2.z);
    y.w = lk(gg.w*d3*r + b2.w);
    ((float4*)g_feat)[(size_t)n*256+tid] = y;
    float4 a = ((float4*)g_acc)[(size_t)n*256+tid];
    a.x+=y.x; a.y+=y.y; a.z+=y.z; a.w+=y.w;
    ((float4*)g_acc)[(size_t)n*256+tid] = a;
    if (a1next){
        float4 av = ((const float4*)a1next)[tid];
        float p = y.x*av.x + y.y*av.y + y.z*av.z + y.w*av.w;
        p = block_reduce_256(p, sm);
        if (tid==0) g_su[n]=p;
    }
}

// ---------------- surface path ----------------
__global__ void surf_lin_kernel(const float* __restrict__ sf,
                                const float* __restrict__ W,
                                const float* __restrict__ b){
    int c  = threadIdx.x & 63;
    int ry = threadIdx.x >> 6;
    int row0 = blockIdx.x * 64;
    float w0=W[c], w1=W[64+c], w2=W[128+c], bc=b[c];
    float ls=0.f, lss=0.f;
    for (int r=ry; r<64; r+=4){
        int row = row0 + r;
        float x0=sf[row*3], x1=sf[row*3+1], x2=sf[row*3+2];
        float y = fmaf(x0,w0, fmaf(x1,w1, fmaf(x2,w2, bc)));
        g_surfy[row*64+c]=y; ls+=y; lss+=y*y;
    }
    __shared__ float ss[256], sq[256];
    ss[threadIdx.x]=ls; sq[threadIdx.x]=lss;
    __syncthreads();
    if (ry==0){
        float t  = ss[c]+ss[64+c]+ss[128+c]+ss[192+c];
        float t2 = sq[c]+sq[64+c]+sq[128+c]+sq[192+c];
        atomicAdd(&g_stats[c], t);
        atomicAdd(&g_stats[64+c], t2);
    }
}

__global__ void finalize_stats_kernel(int which, float n){
    float* st = which ? g_stats2 : g_stats;
    int c = threadIdx.x;
    float mu  = st[c] / n;
    float var = st[64+c]/n - mu*mu;
    st[c]   = mu;
    st[64+c]= rsqrtf(fmaxf(var,0.f)+EPSV);
}

__global__ void surf_norm_scatter_kernel(const int* __restrict__ surf_res,
                                         const float* __restrict__ g,
                                         const float* __restrict__ beta){
    int idx = blockIdx.x*256 + threadIdx.x;
    int row = idx >> 6, c = idx & 63;
    float y = g_surfy[idx];
    float v = lk(g[c]*(y - g_stats[c])*g_stats[64+c] + beta[c]);
    int t = surf_res[row];
    atomicAdd(&g_ressum[t*64 + c], v);
    if (c==0) atomicAdd(&g_rescnt[t], 1.f);
}

// ---------------- final heads ----------------
__global__ void prot_kernel(const float* __restrict__ g,
                            const float* __restrict__ b,
                            float* __restrict__ out){
    int gr = blockIdx.x, c = threadIdx.x;
    const float* base = g_nf + (size_t)gr*512*64;
    float s = 0.f;
    for (int r=0;r<512;r++) s += base[r*64+c];
    float x = s*(1.f/512.f);
    __shared__ float sm[64];
    __shared__ float s_mu, s_r;
    sm[c]=x; __syncthreads();
    if (c==0){ float t=0.f; for (int i=0;i<64;i++) t+=sm[i]; s_mu=t*(1.f/64.f); }
    __syncthreads();
    float d = x - s_mu;
    sm[c]=d*d; __syncthreads();
    if (c==0){ float t=0.f; for (int i=0;i<64;i++) t+=sm[i]; s_r=rsqrtf(t*(1.f/64.f)+EPSV); }
    __syncthreads();
    out[gr*64+c] = lk(g[c]*d*s_r + b[c]);
}

__global__ void ns_a_kernel(const int* __restrict__ uniq,
                            const float* __restrict__ dw,
                            const float* __restrict__ db){
    __shared__ float s_wd[128*64];
    __shared__ float z_s[128];
    int tid = threadIdx.x;
    for (int i=tid; i<128*64; i+=64) s_wd[i]=dw[i];
    float bc = db[tid];
    float ls=0.f, lss=0.f;
    __syncthreads();
    int row0 = blockIdx.x*64;
    for (int r=0;r<64;r++){
        int row = row0 + r;
        if (row >= NUNIQ) break;
        int u = uniq[row];
        z_s[tid]    = g_nf[(size_t)u*64 + tid];
        z_s[64+tid] = g_ressum[(size_t)u*64 + tid] / fmaxf(g_rescnt[u], 1.f);
        __syncthreads();
        float y = bc;
        #pragma unroll 8
        for (int k=0;k<128;k++) y = fmaf(z_s[k], s_wd[k*64+tid], y);
        g_y2[(size_t)row*64+tid] = y;
        ls += y; lss += y*y;
        __syncthreads();
    }
    atomicAdd(&g_stats2[tid], ls);
    atomicAdd(&g_stats2[64+tid], lss);
}

__global__ void ns_norm_scatter_kernel(const int* __restrict__ res_batch,
                                       const float* __restrict__ g,
                                       const float* __restrict__ beta){
    int idx = blockIdx.x*256 + threadIdx.x;
    int row = idx >> 6, c = idx & 63;
    float y = g_y2[idx];
    float v = lk(g[c]*(y - g_stats2[c])*g_stats2[64+c] + beta[c]);
    int t = res_batch[row];
    atomicAdd(&g_nssum[t*64 + c], v);
    if (c==0) atomicAdd(&g_nscnt[t], 1.f);
}

__global__ void ns_final_kernel(const float* __restrict__ bng,
                                const float* __restrict__ bnb,
                                float* __restrict__ out){
    int tid = threadIdx.x;
    int gr = tid >> 6, c = tid & 63;
    float v = g_nssum[tid] / fmaxf(g_nscnt[gr], 1.f);
    __shared__ float sm[1024];
    __shared__ float s_mu[64], s_r[64];
    sm[tid]=v; __syncthreads();
    if (gr==0){
        float t=0.f, t2=0.f;
        for (int r=0;r<16;r++){ float x=sm[r*64+c]; t+=x; t2+=x*x; }
        float mu = t*(1.f/16.f);
        s_mu[c]=mu;
        s_r[c]=rsqrtf(fmaxf(t2*(1.f/16.f)-mu*mu,0.f)+EPSV);
    }
    __syncthreads();
    out[16*64 + tid] = lk(bng[c]*(v - s_mu[c])*s_r[c] + bnb[c]);
}

// ---------------- host ----------------
extern "C" void kernel_launch(void* const* d_in, const int* in_sizes, int n_in,
                              void* d_out, int out_size){
    const int*   ei         = (const int*)  d_in[0];
    const float* n_feats    = (const float*)d_in[1];
    const float* surf_feats = (const float*)d_in[3];
    const int*   surf_res   = (const int*)  d_in[4];
    const int*   res_batch  = (const int*)  d_in[5];
    const int*   uniq       = (const int*)  d_in[6];
    const float* surf_up_w  = (const float*)d_in[7];
    const float* surf_up_b  = (const float*)d_in[8];
    const float* surf_up_g  = (const float*)d_in[9];
    const float* surf_up_be = (const float*)d_in[10];
    const float* a_w        = (const float*)d_in[11];
    const float* lin_w      = (const float*)d_in[12];
    const float* lin_b      = (const float*)d_in[13];
    const float* ln_g       = (const float*)d_in[14];
    const float* ln_b       = (const float*)d_in[15];
    const float* hid_w      = (const float*)d_in[16];
    const float* hid_b      = (const float*)d_in[17];
    const float* down_w     = (const float*)d_in[18];
    const float* down_b     = (const float*)d_in[19];
    const float* down_g     = (const float*)d_in[20];
    const float* down_be    = (const float*)d_in[21];
    const float* prot_ln_g  = (const float*)d_in[22];
    const float* prot_ln_b  = (const float*)d_in[23];
    const float* surf_bn_g  = (const float*)d_in[24];
    const float* surf_bn_b  = (const float*)d_in[25];
    float* out = (float*)d_out;

    cudaFuncSetAttribute(mma_main_kernel,
                         cudaFuncAttributeMaxDynamicSharedMemorySize, MAIN_SMEM);
    cudaFuncSetAttribute(mma_hid_kernel,
                         cudaFuncAttributeMaxDynamicSharedMemorySize, HID_SMEM);

    zero_kernel<<<(NNODES*HID)/256, 256>>>();                       // 1
    degfill_kernel<<<1, 1024>>>(ei);                                // 2
    init_su_kernel<<<NNODES, 256>>>(n_feats, a_w, lin_w);           // 3

    for (int l=0; l<4; l++){
        smagg_kernel<<<NNODES, 256>>>();                            // 4 <- profiled (l=0)
        mma_main_kernel<<<dim3(DIMF/128, NNODES/128), 256, MAIN_SMEM>>>(l);
        const float* a1n = (l<3) ? (a_w + (size_t)(l+1)*2*DIMF) : nullptr;
        ln_su_kernel<<<NNODES, 256>>>(lin_b + (size_t)l*DIMF,
                                      ln_g + (size_t)l*DIMF,
                                      ln_b + (size_t)l*DIMF, a1n);
    }

    mma_hid_kernel<<<dim3(1, NNODES/64), 256, HID_SMEM>>>(hid_w, hid_b);
    prot_kernel<<<NGRAPH, 64>>>(prot_ln_g, prot_ln_b, out);

    surf_lin_kernel<<<NSURF/64, 256>>>(surf_feats, surf_up_w, surf_up_b);
    finalize_stats_kernel<<<1,64>>>(0, (float)NSURF);
    surf_norm_scatter_kernel<<<(NSURF*HID)/256, 256>>>(surf_res, surf_up_g, surf_up_be);

    ns_a_kernel<<<(NUNIQ+63)/64, 64>>>(uniq, down_w, down_b);
    finalize_stats_kernel<<<1,64>>>(1, (float)NUNIQ);
    ns_norm_scatter_kernel<<<(NUNIQ*HID)/256, 256>>>(res_batch, down_g, down_be);
    ns_final_kernel<<<1,1024>>>(surf_bn_g, surf_bn_b, out);
}

// round 14
// speedup vs baseline: 1.5730x; 1.1580x over previous
#include <cuda_runtime.h>
#include <cuda_fp16.h>
#include <cstdint>
#include <math.h>

#define NNODES 8192
#define NEDGES 65536
#define NSURF  40000
#define NUNIQ  6000
#define NGRAPH 16
#define DIMF   1024
#define HID    64
#define EPSV   1e-5f
#define SLOPE  0.01f

// ---------------- scratch (device globals; referenced ONLY in device code) ----------------
__device__ __half   g_feath[NNODES*DIMF];        // fp16 features (gather source)
__device__ float    g_acc [NNODES*DIMF];
__device__ __half   g_aggh[NNODES*DIMF];         // fp16 A operand, row-major [m][k]
__device__ __half2  g_bwh [4*512*1024];          // fp16 B weights, [layer][k/2][n] pair-interleaved
__device__ float    g_gemm[NNODES*DIMF];
__device__ float    g_surfy[NSURF*HID];
__device__ float    g_ressum[NNODES*HID];
__device__ float    g_rescnt[NNODES];
__device__ float    g_su[NNODES];
__device__ int      g_csru[NEDGES];
__device__ int      g_rowptr[NNODES+1];
__device__ float    g_stats [2*HID];
__device__ float    g_stats2[2*HID];
__device__ float    g_nf[NNODES*HID];
__device__ float    g_y2[NUNIQ*HID];
__device__ float    g_nssum[NGRAPH*HID];
__device__ float    g_nscnt[NGRAPH];

__device__ __forceinline__ float lk(float x){ return x >= 0.f ? x : SLOPE*x; }

__device__ __forceinline__ unsigned f2tf32(float f){
    unsigned r;
    asm("cvt.rna.tf32.f32 %0, %1;" : "=r"(r) : "f"(f));
    return r;
}

__device__ __forceinline__ float block_reduce_256(float v, float* sm){
    #pragma unroll
    for (int o=16;o>0;o>>=1) v += __shfl_xor_sync(0xffffffffu, v, o);
    int warp = threadIdx.x>>5, lane = threadIdx.x&31;
    if (lane==0) sm[warp]=v;
    __syncthreads();
    if (warp==0){
        v = (lane<8)? sm[lane] : 0.f;
        #pragma unroll
        for (int o=4;o>0;o>>=1) v += __shfl_xor_sync(0xffffffffu, v, o);
        if (lane==0) sm[0]=v;
    }
    __syncthreads();
    float r = sm[0];
    __syncthreads();
    return r;
}

__device__ __forceinline__ float block_reduce_max_256(float v, float* sm){
    #pragma unroll
    for (int o=16;o>0;o>>=1) v = fmaxf(v, __shfl_xor_sync(0xffffffffu, v, o));
    int warp = threadIdx.x>>5, lane = threadIdx.x&31;
    if (lane==0) sm[warp]=v;
    __syncthreads();
    if (warp==0){
        v = (lane<8)? sm[lane] : -1e30f;
        #pragma unroll
        for (int o=4;o>0;o>>=1) v = fmaxf(v, __shfl_xor_sync(0xffffffffu, v, o));
        if (lane==0) sm[0]=v;
    }
    __syncthreads();
    float r = sm[0];
    __syncthreads();
    return r;
}

// ---------------- launch 1: zeroing ----------------
__global__ void zero_kernel(){
    int i = blockIdx.x*256 + threadIdx.x;
    if (i < NNODES*HID) g_ressum[i] = 0.f;
    if (i < NNODES) g_rescnt[i]=0.f;
    if (i < 2*HID){ g_stats[i]=0.f; g_stats2[i]=0.f; }
    if (i < NGRAPH*HID) g_nssum[i]=0.f;
    if (i < NGRAPH) g_nscnt[i]=0.f;
}

// ---------------- launch 2: fused degree histogram + scan + CSR fill ----------------
__global__ void degfill_kernel(const int* __restrict__ ei){
    __shared__ int cnt[NNODES];
    __shared__ int sm[1024];
    int tid = threadIdx.x;
    for (int i=tid; i<NNODES; i+=1024) cnt[i]=0;
    __syncthreads();
    for (int e=tid; e<NEDGES; e+=1024) atomicAdd(&cnt[ei[NEDGES+e]], 1);
    __syncthreads();
    int base = tid*8;
    int loc[8]; int s=0;
    #pragma unroll
    for (int j=0;j<8;j++){ loc[j]=s; s += cnt[base+j]; }
    sm[tid]=s; __syncthreads();
    for (int off=1; off<1024; off<<=1){
        int t = (tid>=off) ? sm[tid-off] : 0;
        __syncthreads();
        sm[tid]+=t;
        __syncthreads();
    }
    int excl = sm[tid]-s;
    int st[8];
    #pragma unroll
    for (int j=0;j<8;j++){ st[j] = excl + loc[j]; g_rowptr[base+j] = st[j]; }
    if (tid==1023) g_rowptr[NNODES] = sm[1023];
    __syncthreads();
    #pragma unroll
    for (int j=0;j<8;j++) cnt[base+j] = st[j];
    __syncthreads();
    for (int e=tid; e<NEDGES; e+=1024){
        int v = ei[NEDGES+e];
        int p = atomicAdd(&cnt[v], 1);
        g_csru[p] = ei[e];
    }
}

// ---------------- launch 3: init copy + su(layer0) + weight->fp16 pair conversion ----------------
__global__ void init_su_kernel(const float* __restrict__ nf,
                               const float* __restrict__ a1,
                               const float* __restrict__ lw){
    int n = blockIdx.x, tid = threadIdx.x;
    float4 v = ((const float4*)nf)[(size_t)n*256+tid];
    // fp16 feature copy (gather source)
    __half2 f0 = __floats2half2_rn(v.x, v.y);
    __half2 f1 = __floats2half2_rn(v.z, v.w);
    __half2* fd = (__half2*)(g_feath + (size_t)n*DIMF + tid*4);
    fd[0]=f0; fd[1]=f1;
    ((float4*)g_acc)[(size_t)n*256+tid]=v;
    {
        size_t idx = (size_t)n*256 + tid;
        int l   = (int)(idx >> 19);
        int rem = (int)(idx & 524287);
        int k2  = rem >> 10;
        int nn  = rem & 1023;
        const float* base = lw + ((size_t)l << 20);
        float v0 = base[(size_t)(2*k2  )*1024 + nn];
        float v1 = base[(size_t)(2*k2+1)*1024 + nn];
        g_bwh[idx] = __floats2half2_rn(v0, v1);
    }
    float4 a = ((const float4*)a1)[tid];
    float p = v.x*a.x + v.y*a.y + v.z*a.z + v.w*a.w;
    __shared__ float sm[32];
    p = block_reduce_256(p, sm);
    if (tid==0) g_su[n]=p;
}

// ---------------- launch 4 (profiled): fused edge-softmax + aggregate (fp16 gather) ----------------
__global__ void smagg_kernel(){
    int n = blockIdx.x, tid = threadIdx.x;
    int s = g_rowptr[n], e = g_rowptr[n+1];
    __shared__ float s_w[256]; __shared__ int s_u[256];
    __shared__ float red[32];
    float m = -1e30f;
    for (int j=s+tid; j<e; j+=256) m = fmaxf(m, g_su[g_csru[j]]);
    m = block_reduce_max_256(m, red);
    float lsum = 0.f;
    float4 acc = make_float4(0.f,0.f,0.f,0.f);
    for (int base=s; base<e; base+=256){
        int j = base + tid;
        if (j<e){
            int u = g_csru[j];
            float ex = __expf(g_su[u] - m);
            s_w[tid]=ex; s_u[tid]=u; lsum += ex;
        }
        __syncthreads();
        int cnt = min(256, e-base);
        for (int t=0;t<cnt;t++){
            float wv = s_w[t]; int u = s_u[t];
            uint2 hv = *(const uint2*)(g_feath + (size_t)u*DIMF + tid*4);
            float2 f01 = __half22float2(*(const __half2*)&hv.x);
            float2 f23 = __half22float2(*(const __half2*)&hv.y);
            acc.x += wv*f01.x; acc.y += wv*f01.y;
            acc.z += wv*f23.x; acc.w += wv*f23.y;
        }
        __syncthreads();
    }
    float total = block_reduce_256(lsum, red);
    if (total > 0.f){
        float inv = 1.f/total;
        acc.x*=inv; acc.y*=inv; acc.z*=inv; acc.w*=inv;
    }
    __half2 h0 = __floats2half2_rn(acc.x, acc.y);
    __half2 h1 = __floats2half2_rn(acc.z, acc.w);
    __half2* dst = (__half2*)(g_aggh + (size_t)n*DIMF + tid*4);
    dst[0]=h0; dst[1]=h1;
}

// ---------------- launch 5: main fp16 GEMM (mma.sync m16n8k16) ----------------
#define STG  3
#define PA2  20
#define PB2  136
#define ASZ2 (128*PA2)
#define BSZ2 (16*PB2)
#define MAIN_SMEM (STG*(ASZ2+BSZ2)*4)

__global__ void __launch_bounds__(256,2) mma_main_kernel(int layer){
    extern __shared__ unsigned dyn[];
    unsigned* AsB = dyn;
    unsigned* BsB = dyn + STG*ASZ2;
    const __half*  A = g_aggh;
    const unsigned* B = (const unsigned*)(g_bwh + (size_t)layer*524288);

    const int tid = threadIdx.x;
    const int warp = tid>>5, lane = tid&31;
    const int wm = warp>>2, wn = warp&3;
    const int gid = lane>>2, qid = lane&3;
    const int bm0 = blockIdx.y*128, bn0 = blockIdx.x*128;

    auto issue = [&](int it){
        unsigned* As = AsB + (it%STG)*ASZ2;
        unsigned* Bs = BsB + (it%STG)*BSZ2;
        int k0 = it*32;
        int k20 = it*16;
        #pragma unroll
        for (int a=0;a<2;a++){
            int chunk = tid + a*256;
            int row = chunk>>2, c16 = chunk&3;
            unsigned dst = (unsigned)__cvta_generic_to_shared(&As[row*PA2 + c16*4]);
            asm volatile("cp.async.cg.shared.global [%0], [%1], 16;"
                         :: "r"(dst), "l"(A + (size_t)(bm0+row)*DIMF + k0 + c16*8));
        }
        #pragma unroll
        for (int b=0;b<2;b++){
            int chunk = tid + b*256;
            int row = chunk>>5, c4 = chunk&31;
            unsigned dst = (unsigned)__cvta_generic_to_shared(&Bs[row*PB2 + c4*4]);
            asm volatile("cp.async.cg.shared.global [%0], [%1], 16;"
                         :: "r"(dst), "l"(B + (size_t)(k20+row)*1024 + bn0 + c4*4));
        }
        asm volatile("cp.async.commit_group;" ::: "memory");
    };

    float acc[4][4][4];
    #pragma unroll
    for (int i=0;i<4;i++)
        #pragma unroll
        for (int j=0;j<4;j++)
            #pragma unroll
            for (int q=0;q<4;q++) acc[i][j][q]=0.f;

    issue(0); issue(1);

    const int NIT = DIMF/32;
    for (int it=0; it<NIT; it++){
        asm volatile("cp.async.wait_group 1;" ::: "memory");
        __syncthreads();
        if (it+2 < NIT) issue(it+2);
        const unsigned* curA = AsB + (it%STG)*ASZ2;
        const unsigned* curB = BsB + (it%STG)*BSZ2;
        #pragma unroll
        for (int kk=0; kk<2; kk++){
            unsigned af[4][4], bf[4][2];
            #pragma unroll
            for (int i=0;i<4;i++){
                int r0 = wm*64 + i*16 + gid;
                int c0 = kk*8 + qid;
                af[i][0]=curA[ r0   *PA2 + c0  ];
                af[i][1]=curA[(r0+8)*PA2 + c0  ];
                af[i][2]=curA[ r0   *PA2 + c0+4];
                af[i][3]=curA[(r0+8)*PA2 + c0+4];
            }
            #pragma unroll
            for (int j=0;j<4;j++){
                int cc = wn*32 + j*8 + gid;
                bf[j][0]=curB[(kk*8+qid  )*PB2 + cc];
                bf[j][1]=curB[(kk*8+qid+4)*PB2 + cc];
            }
            #pragma unroll
            for (int i=0;i<4;i++)
                #pragma unroll
                for (int j=0;j<4;j++){
                    asm volatile(
                        "mma.sync.aligned.m16n8k16.row.col.f32.f16.f16.f32 "
                        "{%0,%1,%2,%3}, {%4,%5,%6,%7}, {%8,%9}, {%0,%1,%2,%3};"
                        : "+f"(acc[i][j][0]), "+f"(acc[i][j][1]),
                          "+f"(acc[i][j][2]), "+f"(acc[i][j][3])
                        : "r"(af[i][0]), "r"(af[i][1]), "r"(af[i][2]), "r"(af[i][3]),
                          "r"(bf[j][0]), "r"(bf[j][1]));
                }
        }
    }
    #pragma unroll
    for (int i=0;i<4;i++){
        int r0 = bm0 + wm*64 + i*16 + gid;
        #pragma unroll
        for (int j=0;j<4;j++){
            int cc = bn0 + wn*32 + j*8 + qid*2;
            float2 v0, v1;
            v0.x = acc[i][j][0]; v0.y = acc[i][j][1];
            v1.x = acc[i][j][2]; v1.y = acc[i][j][3];
            *(float2*)(g_gemm + (size_t) r0   *DIMF + cc) = v0;
            *(float2*)(g_gemm + (size_t)(r0+8)*DIMF + cc) = v1;
        }
    }
}

// ---------------- hid GEMM (small; tf32 register-staged path) ----------------
template<int BM,int BN,int BK,int WM,int WN,bool BIAS>
__device__ __forceinline__ void mma_body(
        const float* __restrict__ A, const float* __restrict__ B,
        float* __restrict__ C, int N, int K,
        float alpha, const float* __restrict__ bias,
        unsigned* As, unsigned* Bs){
    constexpr int MT = WM/16, NT = WN/8, KT = BK/8;
    constexpr int WARPS_N = BN/WN;
    constexpr int PA = BK+4;
    constexpr int PB = BN+8;
    constexpr int AREG = BM*BK/1024;
    constexpr int BREG = BK*BN/1024;

    const int tid = threadIdx.x;
    const int warp = tid>>5, lane = tid&31;
    const int wm = warp / WARPS_N, wn = warp % WARPS_N;
    const int gid = lane>>2, qid = lane&3;
    const int bm0 = blockIdx.y*BM, bn0 = blockIdx.x*BN;

    float4 ra[AREG], rb[BREG];

    auto ldg_tile = [&](int k0){
        #pragma unroll
        for (int a=0;a<AREG;a++){
            int i = tid*4 + a*1024;
            int r = i/BK, c = i%BK;
            ra[a] = *(const float4*)(A + (size_t)(bm0+r)*K + k0 + c);
        }
        #pragma unroll
        for (int b=0;b<BREG;b++){
            int i = tid*4 + b*1024;
            int r = i/BN, c = i%BN;
            rb[b] = *(const float4*)(B + (size_t)(k0+r)*N + bn0 + c);
        }
    };
    auto sts_tile = [&](){
        #pragma unroll
        for (int a=0;a<AREG;a++){
            int i = tid*4 + a*1024;
            int r = i/BK, c = i%BK;
            uint4 p;
            p.x=f2tf32(ra[a].x); p.y=f2tf32(ra[a].y);
            p.z=f2tf32(ra[a].z); p.w=f2tf32(ra[a].w);
            *(uint4*)&As[r*PA+c] = p;
        }
        #pragma unroll
        for (int b=0;b<BREG;b++){
            int i = tid*4 + b*1024;
            int r = i/BN, c = i%BN;
            uint4 p;
            p.x=f2tf32(rb[b].x); p.y=f2tf32(rb[b].y);
            p.z=f2tf32(rb[b].z); p.w=f2tf32(rb[b].w);
            *(uint4*)&Bs[r*PB+c] = p;
        }
    };

    float acc[MT][NT][4];
    #pragma unroll
    for (int i=0;i<MT;i++)
        #pragma unroll
        for (int j=0;j<NT;j++)
            #pragma unroll
            for (int q=0;q<4;q++) acc[i][j][q]=0.f;

    ldg_tile(0);
    sts_tile();
    __syncthreads();

    const int NIT = K/BK;
    for (int it=0; it<NIT; it++){
        if (it+1 < NIT) ldg_tile((it+1)*BK);
        #pragma unroll
        for (int kk=0; kk<KT; kk++){
            unsigned af[MT][4], bf[NT][2];
            #pragma unroll
            for (int i=0;i<MT;i++){
                int r0 = wm*WM + i*16 + gid;
                int c0 = kk*8 + qid;
                af[i][0]=As[ r0   *PA + c0  ];
                af[i][1]=As[(r0+8)*PA + c0  ];
                af[i][2]=As[ r0   *PA + c0+4];
                af[i][3]=As[(r0+8)*PA + c0+4];
            }
            #pragma unroll
            for (int j=0;j<NT;j++){
                int cc = wn*WN + j*8 + gid;
                bf[j][0]=Bs[(kk*8+qid  )*PB + cc];
                bf[j][1]=Bs[(kk*8+qid+4)*PB + cc];
            }
            #pragma unroll
            for (int i=0;i<MT;i++)
                #pragma unroll
                for (int j=0;j<NT;j++){
                    asm volatile(
                        "mma.sync.aligned.m16n8k8.row.col.f32.tf32.tf32.f32 "
                        "{%0,%1,%2,%3}, {%4,%5,%6,%7}, {%8,%9}, {%0,%1,%2,%3};"
                        : "+f"(acc[i][j][0]), "+f"(acc[i][j][1]),
                          "+f"(acc[i][j][2]), "+f"(acc[i][j][3])
                        : "r"(af[i][0]), "r"(af[i][1]), "r"(af[i][2]), "r"(af[i][3]),
                          "r"(bf[j][0]), "r"(bf[j][1]));
                }
        }
        __syncthreads();
        if (it+1 < NIT){
            sts_tile();
            __syncthreads();
        }
    }
    #pragma unroll
    for (int i=0;i<MT;i++){
        int r0 = bm0 + wm*WM + i*16 + gid;
        #pragma unroll
        for (int j=0;j<NT;j++){
            int cc = bn0 + wn*WN + j*8 + qid*2;
            float b0 = BIAS ? bias[cc] : 0.f;
            float b1 = BIAS ? bias[cc+1] : 0.f;
            float2 v0, v1;
            v0.x = alpha*acc[i][j][0] + b0;
            v0.y = alpha*acc[i][j][1] + b1;
            v1.x = alpha*acc[i][j][2] + b0;
            v1.y = alpha*acc[i][j][3] + b1;
            *(float2*)(C + (size_t) r0   *N + cc) = v0;
            *(float2*)(C + (size_t)(r0+8)*N + cc) = v1;
        }
    }
}

#define HID_SMEM ((64*36 + 32*72)*4)
__global__ void __launch_bounds__(256) mma_hid_kernel(const float* __restrict__ Bw,
                                                      const float* __restrict__ bias){
    extern __shared__ unsigned dyn[];
    unsigned* As = dyn;
    unsigned* Bs = dyn + 64*36;
    mma_body<64,64,32,16,32,true>(g_acc, Bw, g_nf, HID, DIMF,
                                  0.2f, bias, As, Bs);
}

// ---------------- per layer: LN + leaky + feat(fp16)/acc update + next su ----------------
__global__ void ln_su_kernel(const float* __restrict__ linb,
                             const float* __restrict__ lng,
                             const float* __restrict__ lnb,
                             const float* __restrict__ a1next){
    int n = blockIdx.x, tid = threadIdx.x;
    float4 x = ((const float4*)g_gemm)[(size_t)n*256+tid];
    float4 bb = ((const float4*)linb)[tid];
    x.x+=bb.x; x.y+=bb.y; x.z+=bb.z; x.w+=bb.w;
    __shared__ float sm[32];
    float s = x.x+x.y+x.z+x.w;
    s = block_reduce_256(s, sm);
    float mu = s*(1.f/1024.f);
    float d0=x.x-mu, d1=x.y-mu, d2=x.z-mu, d3=x.w-mu;
    float q = d0*d0+d1*d1+d2*d2+d3*d3;
    q = block_reduce_256(q, sm);
    float r = rsqrtf(q*(1.f/1024.f)+EPSV);
    float4 gg = ((const float4*)lng)[tid];
    float4 b2 = ((const float4*)lnb)[tid];
    float4 y;
    y.x = lk(gg.x*d0*r + b2.x);
    y.y = lk(gg.y*d1*r + b2.y);
    y.z = lk(gg.z*d2*r + b2.z);
    y.w = lk(gg.w*d3*r + b2.w);
    __half2 h0 = __floats2half2_rn(y.x, y.y);
    __half2 h1 = __floats2half2_rn(y.z, y.w);
    __half2* fd = (__half2*)(g_feath + (size_t)n*DIMF + tid*4);
    fd[0]=h0; fd[1]=h1;
    float4 a = ((float4*)g_acc)[(size_t)n*256+tid];
    a.x+=y.x; a.y+=y.y; a.z+=y.z; a.w+=y.w;
    ((float4*)g_acc)[(size_t)n*256+tid] = a;
    if (a1next){
        float4 av = ((const float4*)a1next)[tid];
        float p = y.x*av.x + y.y*av.y + y.z*av.z + y.w*av.w;
        p = block_reduce_256(p, sm);
        if (tid==0) g_su[n]=p;
    }
}

// ---------------- surface path ----------------
__global__ void surf_lin_kernel(const float* __restrict__ sf,
                                const float* __restrict__ W,
                                const float* __restrict__ b){
    int c  = threadIdx.x & 63;
    int ry = threadIdx.x >> 6;
    int row0 = blockIdx.x * 64;
    float w0=W[c], w1=W[64+c], w2=W[128+c], bc=b[c];
    float ls=0.f, lss=0.f;
    for (int r=ry; r<64; r+=4){
        int row = row0 + r;
        float x0=sf[row*3], x1=sf[row*3+1], x2=sf[row*3+2];
        float y = fmaf(x0,w0, fmaf(x1,w1, fmaf(x2,w2, bc)));
        g_surfy[row*64+c]=y; ls+=y; lss+=y*y;
    }
    __shared__ float ss[256], sq[256];
    ss[threadIdx.x]=ls; sq[threadIdx.x]=lss;
    __syncthreads();
    if (ry==0){
        float t  = ss[c]+ss[64+c]+ss[128+c]+ss[192+c];
        float t2 = sq[c]+sq[64+c]+sq[128+c]+sq[192+c];
        atomicAdd(&g_stats[c], t);
        atomicAdd(&g_stats[64+c], t2);
    }
}

__global__ void finalize_stats_kernel(int which, float n){
    float* st = which ? g_stats2 : g_stats;
    int c = threadIdx.x;
    float mu  = st[c] / n;
    float var = st[64+c]/n - mu*mu;
    st[c]   = mu;
    st[64+c]= rsqrtf(fmaxf(var,0.f)+EPSV);
}

__global__ void surf_norm_scatter_kernel(const int* __restrict__ surf_res,
                                         const float* __restrict__ g,
                                         const float* __restrict__ beta){
    int idx = blockIdx.x*256 + threadIdx.x;
    int row = idx >> 6, c = idx & 63;
    float y = g_surfy[idx];
    float v = lk(g[c]*(y - g_stats[c])*g_stats[64+c] + beta[c]);
    int t = surf_res[row];
    atomicAdd(&g_ressum[t*64 + c], v);
    if (c==0) atomicAdd(&g_rescnt[t], 1.f);
}

// ---------------- final heads ----------------
__global__ void prot_kernel(const float* __restrict__ g,
                            const float* __restrict__ b,
                            float* __restrict__ out){
    int gr = blockIdx.x;
    int tid = threadIdx.x;               // 256: 4 row-chunks x 64 cols
    int c = tid & 63, chunk = tid >> 6;
    const float* base = g_nf + (size_t)gr*512*64;
    float s = 0.f;
    for (int r=chunk*128; r<(chunk+1)*128; r++) s += base[r*64+c];
    __shared__ float part[256];
    part[tid]=s; __syncthreads();
    if (chunk==0){
        float x = (part[c]+part[64+c]+part[128+c]+part[192+c])*(1.f/512.f);
        __shared__ float sm[64];
        __shared__ float s_mu, s_r;
        sm[c]=x; __syncthreads();
        if (c==0){ float t=0.f; for (int i=0;i<64;i++) t+=sm[i]; s_mu=t*(1.f/64.f); }
        __syncthreads();
        float d = x - s_mu;
        sm[c]=d*d; __syncthreads();
        if (c==0){ float t=0.f; for (int i=0;i<64;i++) t+=sm[i]; s_r=rsqrtf(t*(1.f/64.f)+EPSV); }
        __syncthreads();
        out[gr*64+c] = lk(g[c]*d*s_r + b[c]);
    }
}

// ns_a: 256 threads, 16 rows per block, 4 rows in flight
__global__ void __launch_bounds__(256) ns_a_kernel(const int* __restrict__ uniq,
                            const float* __restrict__ dw,
                            const float* __restrict__ db){
    __shared__ float s_wd[128*64];
    __shared__ float z_s[4][128];
    int tid = threadIdx.x;
    int c = tid & 63, rq = tid >> 6;       // 4 row-groups
    for (int i=tid; i<128*64; i+=256) s_wd[i]=dw[i];
    float bc = db[c];
    float ls=0.f, lss=0.f;
    __syncthreads();
    int row0 = blockIdx.x*16;
    for (int rr=rq; rr<16; rr+=4){
        int row = row0 + rr;
        if (row < NUNIQ){
            int u = uniq[row];
            // 64 threads of this quad load 128 z values (2 each)
            z_s[rq][c]    = g_nf[(size_t)u*64 + c];
            z_s[rq][64+c] = g_ressum[(size_t)u*64 + c] / fmaxf(g_rescnt[u], 1.f);
        }
        __syncthreads();
        if (row < NUNIQ){
            float y = bc;
            #pragma unroll 8
            for (int k=0;k<128;k++) y = fmaf(z_s[rq][k], s_wd[k*64+c], y);
            g_y2[(size_t)row*64+c] = y;
            ls += y; lss += y*y;
        }
        __syncthreads();
    }
    atomicAdd(&g_stats2[c], ls);
    atomicAdd(&g_stats2[64+c], lss);
}

__global__ void ns_norm_scatter_kernel(const int* __restrict__ res_batch,
                                       const float* __restrict__ g,
                                       const float* __restrict__ beta){
    int idx = blockIdx.x*256 + threadIdx.x;
    if (idx >= NUNIQ*HID) return;
    int row = idx >> 6, c = idx & 63;
    float y = g_y2[idx];
    float v = lk(g[c]*(y - g_stats2[c])*g_stats2[64+c] + beta[c]);
    int t = res_batch[row];
    atomicAdd(&g_nssum[t*64 + c], v);
    if (c==0) atomicAdd(&g_nscnt[t], 1.f);
}

__global__ void ns_final_kernel(const float* __restrict__ bng,
                                const float* __restrict__ bnb,
                                float* __restrict__ out){
    int tid = threadIdx.x;
    int gr = tid >> 6, c = tid & 63;
    float v = g_nssum[tid] / fmaxf(g_nscnt[gr], 1.f);
    __shared__ float sm[1024];
    __shared__ float s_mu[64], s_r[64];
    sm[tid]=v; __syncthreads();
    if (gr==0){
        float t=0.f, t2=0.f;
        for (int r=0;r<16;r++){ float x=sm[r*64+c]; t+=x; t2+=x*x; }
        float mu = t*(1.f/16.f);
        s_mu[c]=mu;
        s_r[c]=rsqrtf(fmaxf(t2*(1.f/16.f)-mu*mu,0.f)+EPSV);
    }
    __syncthreads();
    out[16*64 + tid] = lk(bng[c]*(v - s_mu[c])*s_r[c] + bnb[c]);
}

// ---------------- host ----------------
extern "C" void kernel_launch(void* const* d_in, const int* in_sizes, int n_in,
                              void* d_out, int out_size){
    const int*   ei         = (const int*)  d_in[0];
    const float* n_feats    = (const float*)d_in[1];
    const float* surf_feats = (const float*)d_in[3];
    const int*   surf_res   = (const int*)  d_in[4];
    const int*   res_batch  = (const int*)  d_in[5];
    const int*   uniq       = (const int*)  d_in[6];
    const float* surf_up_w  = (const float*)d_in[7];
    const float* surf_up_b  = (const float*)d_in[8];
    const float* surf_up_g  = (const float*)d_in[9];
    const float* surf_up_be = (const float*)d_in[10];
    const float* a_w        = (const float*)d_in[11];
    const float* lin_w      = (const float*)d_in[12];
    const float* lin_b      = (const float*)d_in[13];
    const float* ln_g       = (const float*)d_in[14];
    const float* ln_b       = (const float*)d_in[15];
    const float* hid_w      = (const float*)d_in[16];
    const float* hid_b      = (const float*)d_in[17];
    const float* down_w     = (const float*)d_in[18];
    const float* down_b     = (const float*)d_in[19];
    const float* down_g     = (const float*)d_in[20];
    const float* down_be    = (const float*)d_in[21];
    const float* prot_ln_g  = (const float*)d_in[22];
    const float* prot_ln_b  = (const float*)d_in[23];
    const float* surf_bn_g  = (const float*)d_in[24];
    const float* surf_bn_b  = (const float*)d_in[25];
    float* out = (float*)d_out;

    cudaFuncSetAttribute(mma_main_kernel,
                         cudaFuncAttributeMaxDynamicSharedMemorySize, MAIN_SMEM);
    cudaFuncSetAttribute(mma_hid_kernel,
                         cudaFuncAttributeMaxDynamicSharedMemorySize, HID_SMEM);

    zero_kernel<<<(NNODES*HID)/256, 256>>>();                       // 1
    degfill_kernel<<<1, 1024>>>(ei);                                // 2
    init_su_kernel<<<NNODES, 256>>>(n_feats, a_w, lin_w);           // 3

    for (int l=0; l<4; l++){
        smagg_kernel<<<NNODES, 256>>>();                            // 4 <- profiled (l=0)
        mma_main_kernel<<<dim3(DIMF/128, NNODES/128), 256, MAIN_SMEM>>>(l);
        const float* a1n = (l<3) ? (a_w + (size_t)(l+1)*2*DIMF) : nullptr;
        ln_su_kernel<<<NNODES, 256>>>(lin_b + (size_t)l*DIMF,
                                      ln_g + (size_t)l*DIMF,
                                      ln_b + (size_t)l*DIMF, a1n);
    }

    mma_hid_kernel<<<dim3(1, NNODES/64), 256, HID_SMEM>>>(hid_w, hid_b);
    prot_kernel<<<NGRAPH, 256>>>(prot_ln_g, prot_ln_b, out);

    surf_lin_kernel<<<NSURF/64, 256>>>(surf_feats, surf_up_w, surf_up_b);
    finalize_stats_kernel<<<1,64>>>(0, (float)NSURF);
    surf_norm_scatter_kernel<<<(NSURF*HID)/256, 256>>>(surf_res, surf_up_g, surf_up_be);

    ns_a_kernel<<<(NUNIQ+15)/16, 256>>>(uniq, down_w, down_b);
    finalize_stats_kernel<<<1,64>>>(1, (float)NUNIQ);
    ns_norm_scatter_kernel<<<(NUNIQ*HID+255)/256, 256>>>(res_batch, down_g, down_be);
    ns_final_kernel<<<1,1024>>>(surf_bn_g, surf_bn_b, out);
}

// round 15
// speedup vs baseline: 1.5819x; 1.0057x over previous
#include <cuda_runtime.h>
#include <cuda_fp16.h>
#include <cstdint>
#include <math.h>

#define NNODES 8192
#define NEDGES 65536
#define NSURF  40000
#define NUNIQ  6000
#define NGRAPH 16
#define DIMF   1024
#define HID    64
#define EPSV   1e-5f
#define SLOPE  0.01f

// ---------------- scratch (device globals; referenced ONLY in device code) ----------------
__device__ __half   g_feath[NNODES*DIMF];        // fp16 features (gather source)
__device__ float    g_acc [NNODES*DIMF];
__device__ __half   g_aggh[NNODES*DIMF];         // fp16 A operand, row-major [m][k]
__device__ __half2  g_bwh [4*512*1024];          // fp16 B weights, [layer][k/2][n] pair-interleaved
__device__ float    g_gemm[NNODES*DIMF];
__device__ float    g_surfy[NSURF*HID];
__device__ float    g_ressum[NNODES*HID];
__device__ float    g_rescnt[NNODES];
__device__ float    g_su[NNODES];
__device__ float    g_sumax;                     // global max of g_su (softmax shift)
__device__ int      g_csru[NEDGES];
__device__ int      g_rowptr[NNODES+1];
__device__ float    g_stats [2*HID];
__device__ float    g_stats2[2*HID];
__device__ float    g_nf[NNODES*HID];
__device__ float    g_y2[NUNIQ*HID];
__device__ float    g_nssum[NGRAPH*HID];
__device__ float    g_nscnt[NGRAPH];

__device__ __forceinline__ float lk(float x){ return x >= 0.f ? x : SLOPE*x; }

__device__ __forceinline__ unsigned f2tf32(float f){
    unsigned r;
    asm("cvt.rna.tf32.f32 %0, %1;" : "=r"(r) : "f"(f));
    return r;
}

__device__ __forceinline__ void atomicMaxF(float* a, float v){
    int old = __float_as_int(*a);
    while (__int_as_float(old) < v){
        int assumed = old;
        old = atomicCAS((int*)a, assumed, __float_as_int(v));
        if (old == assumed) break;
    }
}

__device__ __forceinline__ float block_reduce_256(float v, float* sm){
    #pragma unroll
    for (int o=16;o>0;o>>=1) v += __shfl_xor_sync(0xffffffffu, v, o);
    int warp = threadIdx.x>>5, lane = threadIdx.x&31;
    if (lane==0) sm[warp]=v;
    __syncthreads();
    if (warp==0){
        v = (lane<8)? sm[lane] : 0.f;
        #pragma unroll
        for (int o=4;o>0;o>>=1) v += __shfl_xor_sync(0xffffffffu, v, o);
        if (lane==0) sm[0]=v;
    }
    __syncthreads();
    float r = sm[0];
    __syncthreads();
    return r;
}

// ---------------- launch 1: zeroing ----------------
__global__ void zero_kernel(){
    int i = blockIdx.x*256 + threadIdx.x;
    if (i < NNODES*HID) g_ressum[i] = 0.f;
    if (i < NNODES) g_rescnt[i]=0.f;
    if (i < 2*HID){ g_stats[i]=0.f; g_stats2[i]=0.f; }
    if (i < NGRAPH*HID) g_nssum[i]=0.f;
    if (i < NGRAPH) g_nscnt[i]=0.f;
}

// ---------------- launch 2: fused degree histogram + scan + CSR fill ----------------
__global__ void degfill_kernel(const int* __restrict__ ei){
    __shared__ int cnt[NNODES];
    __shared__ int sm[1024];
    int tid = threadIdx.x;
    if (tid==0) g_sumax = -1e30f;
    for (int i=tid; i<NNODES; i+=1024) cnt[i]=0;
    __syncthreads();
    for (int e=tid; e<NEDGES; e+=1024) atomicAdd(&cnt[ei[NEDGES+e]], 1);
    __syncthreads();
    int base = tid*8;
    int loc[8]; int s=0;
    #pragma unroll
    for (int j=0;j<8;j++){ loc[j]=s; s += cnt[base+j]; }
    sm[tid]=s; __syncthreads();
    for (int off=1; off<1024; off<<=1){
        int t = (tid>=off) ? sm[tid-off] : 0;
        __syncthreads();
        sm[tid]+=t;
        __syncthreads();
    }
    int excl = sm[tid]-s;
    int st[8];
    #pragma unroll
    for (int j=0;j<8;j++){ st[j] = excl + loc[j]; g_rowptr[base+j] = st[j]; }
    if (tid==1023) g_rowptr[NNODES] = sm[1023];
    __syncthreads();
    #pragma unroll
    for (int j=0;j<8;j++) cnt[base+j] = st[j];
    __syncthreads();
    for (int e=tid; e<NEDGES; e+=1024){
        int v = ei[NEDGES+e];
        int p = atomicAdd(&cnt[v], 1);
        g_csru[p] = ei[e];
    }
}

// ---------------- launch 3: init copy + su(layer0) + weight->fp16 pair conversion ----------------
__global__ void init_su_kernel(const float* __restrict__ nf,
                               const float* __restrict__ a1,
                               const float* __restrict__ lw){
    int n = blockIdx.x, tid = threadIdx.x;
    float4 v = ((const float4*)nf)[(size_t)n*256+tid];
    __half2 f0 = __floats2half2_rn(v.x, v.y);
    __half2 f1 = __floats2half2_rn(v.z, v.w);
    __half2* fd = (__half2*)(g_feath + (size_t)n*DIMF + tid*4);
    fd[0]=f0; fd[1]=f1;
    ((float4*)g_acc)[(size_t)n*256+tid]=v;
    {
        size_t idx = (size_t)n*256 + tid;
        int l   = (int)(idx >> 19);
        int rem = (int)(idx & 524287);
        int k2  = rem >> 10;
        int nn  = rem & 1023;
        const float* base = lw + ((size_t)l << 20);
        float v0 = base[(size_t)(2*k2  )*1024 + nn];
        float v1 = base[(size_t)(2*k2+1)*1024 + nn];
        g_bwh[idx] = __floats2half2_rn(v0, v1);
    }
    float4 a = ((const float4*)a1)[tid];
    float p = v.x*a.x + v.y*a.y + v.z*a.z + v.w*a.w;
    __shared__ float sm[32];
    p = block_reduce_256(p, sm);
    if (tid==0){ g_su[n]=p; atomicMaxF(&g_sumax, p); }
}

// ---------------- launch 4 (profiled): fused edge-softmax + aggregate (global shift) ----------------
__global__ void smagg_kernel(){
    int n = blockIdx.x, tid = threadIdx.x;
    int s = g_rowptr[n], e = g_rowptr[n+1];
    __shared__ float s_w[256]; __shared__ int s_u[256];
    __shared__ float red[32];
    float m = g_sumax;                     // valid softmax shift (global max >= group max)
    float lsum = 0.f;
    float4 acc = make_float4(0.f,0.f,0.f,0.f);
    for (int base=s; base<e; base+=256){
        int j = base + tid;
        if (j<e){
            int u = g_csru[j];
            float ex = __expf(g_su[u] - m);
            s_w[tid]=ex; s_u[tid]=u; lsum += ex;
        }
        __syncthreads();
        int cnt = min(256, e-base);
        for (int t=0;t<cnt;t++){
            float wv = s_w[t]; int u = s_u[t];
            uint2 hv = *(const uint2*)(g_feath + (size_t)u*DIMF + tid*4);
            float2 f01 = __half22float2(*(const __half2*)&hv.x);
            float2 f23 = __half22float2(*(const __half2*)&hv.y);
            acc.x += wv*f01.x; acc.y += wv*f01.y;
            acc.z += wv*f23.x; acc.w += wv*f23.y;
        }
        __syncthreads();
    }
    float total = block_reduce_256(lsum, red);
    if (total > 0.f){
        float inv = 1.f/total;
        acc.x*=inv; acc.y*=inv; acc.z*=inv; acc.w*=inv;
    }
    __half2 h0 = __floats2half2_rn(acc.x, acc.y);
    __half2 h1 = __floats2half2_rn(acc.z, acc.w);
    __half2* dst = (__half2*)(g_aggh + (size_t)n*DIMF + tid*4);
    dst[0]=h0; dst[1]=h1;
}

// ---------------- launch 5: main fp16 GEMM (mma.sync m16n8k16) ----------------
#define STG  3
#define PA2  20
#define PB2  136
#define ASZ2 (128*PA2)
#define BSZ2 (16*PB2)
#define MAIN_SMEM (STG*(ASZ2+BSZ2)*4)

__global__ void __launch_bounds__(256,2) mma_main_kernel(int layer){
    extern __shared__ unsigned dyn[];
    unsigned* AsB = dyn;
    unsigned* BsB = dyn + STG*ASZ2;
    const __half*  A = g_aggh;
    const unsigned* B = (const unsigned*)(g_bwh + (size_t)layer*524288);

    const int tid = threadIdx.x;
    const int warp = tid>>5, lane = tid&31;
    const int wm = warp>>2, wn = warp&3;
    const int gid = lane>>2, qid = lane&3;
    const int bm0 = blockIdx.y*128, bn0 = blockIdx.x*128;

    // reset softmax shift for the NEXT layer's su (smagg of this layer already ran)
    if (blockIdx.x==0 && blockIdx.y==0 && tid==0) g_sumax = -1e30f;

    auto issue = [&](int it){
        unsigned* As = AsB + (it%STG)*ASZ2;
        unsigned* Bs = BsB + (it%STG)*BSZ2;
        int k0 = it*32;
        int k20 = it*16;
        #pragma unroll
        for (int a=0;a<2;a++){
            int chunk = tid + a*256;
            int row = chunk>>2, c16 = chunk&3;
            unsigned dst = (unsigned)__cvta_generic_to_shared(&As[row*PA2 + c16*4]);
            asm volatile("cp.async.cg.shared.global [%0], [%1], 16;"
                         :: "r"(dst), "l"(A + (size_t)(bm0+row)*DIMF + k0 + c16*8));
        }
        #pragma unroll
        for (int b=0;b<2;b++){
            int chunk = tid + b*256;
            int row = chunk>>5, c4 = chunk&31;
            unsigned dst = (unsigned)__cvta_generic_to_shared(&Bs[row*PB2 + c4*4]);
            asm volatile("cp.async.cg.shared.global [%0], [%1], 16;"
                         :: "r"(dst), "l"(B + (size_t)(k20+row)*1024 + bn0 + c4*4));
        }
        asm volatile("cp.async.commit_group;" ::: "memory");
    };

    float acc[4][4][4];
    #pragma unroll
    for (int i=0;i<4;i++)
        #pragma unroll
        for (int j=0;j<4;j++)
            #pragma unroll
            for (int q=0;q<4;q++) acc[i][j][q]=0.f;

    issue(0); issue(1);

    const int NIT = DIMF/32;
    for (int it=0; it<NIT; it++){
        asm volatile("cp.async.wait_group 1;" ::: "memory");
        __syncthreads();
        if (it+2 < NIT) issue(it+2);
        const unsigned* curA = AsB + (it%STG)*ASZ2;
        const unsigned* curB = BsB + (it%STG)*BSZ2;
        #pragma unroll
        for (int kk=0; kk<2; kk++){
            unsigned af[4][4], bf[4][2];
            #pragma unroll
            for (int i=0;i<4;i++){
                int r0 = wm*64 + i*16 + gid;
                int c0 = kk*8 + qid;
                af[i][0]=curA[ r0   *PA2 + c0  ];
                af[i][1]=curA[(r0+8)*PA2 + c0  ];
                af[i][2]=curA[ r0   *PA2 + c0+4];
                af[i][3]=curA[(r0+8)*PA2 + c0+4];
            }
            #pragma unroll
            for (int j=0;j<4;j++){
                int cc = wn*32 + j*8 + gid;
                bf[j][0]=curB[(kk*8+qid  )*PB2 + cc];
                bf[j][1]=curB[(kk*8+qid+4)*PB2 + cc];
            }
            #pragma unroll
            for (int i=0;i<4;i++)
                #pragma unroll
                for (int j=0;j<4;j++){
                    asm volatile(
                        "mma.sync.aligned.m16n8k16.row.col.f32.f16.f16.f32 "
                        "{%0,%1,%2,%3}, {%4,%5,%6,%7}, {%8,%9}, {%0,%1,%2,%3};"
                        : "+f"(acc[i][j][0]), "+f"(acc[i][j][1]),
                          "+f"(acc[i][j][2]), "+f"(acc[i][j][3])
                        : "r"(af[i][0]), "r"(af[i][1]), "r"(af[i][2]), "r"(af[i][3]),
                          "r"(bf[j][0]), "r"(bf[j][1]));
                }
        }
    }
    #pragma unroll
    for (int i=0;i<4;i++){
        int r0 = bm0 + wm*64 + i*16 + gid;
        #pragma unroll
        for (int j=0;j<4;j++){
            int cc = bn0 + wn*32 + j*8 + qid*2;
            float2 v0, v1;
            v0.x = acc[i][j][0]; v0.y = acc[i][j][1];
            v1.x = acc[i][j][2]; v1.y = acc[i][j][3];
            *(float2*)(g_gemm + (size_t) r0   *DIMF + cc) = v0;
            *(float2*)(g_gemm + (size_t)(r0+8)*DIMF + cc) = v1;
        }
    }
}

// ---------------- hid GEMM (small; tf32 register-staged path) ----------------
template<int BM,int BN,int BK,int WM,int WN,bool BIAS>
__device__ __forceinline__ void mma_body(
        const float* __restrict__ A, const float* __restrict__ B,
        float* __restrict__ C, int N, int K,
        float alpha, const float* __restrict__ bias,
        unsigned* As, unsigned* Bs){
    constexpr int MT = WM/16, NT = WN/8, KT = BK/8;
    constexpr int WARPS_N = BN/WN;
    constexpr int PA = BK+4;
    constexpr int PB = BN+8;
    constexpr int AREG = BM*BK/1024;
    constexpr int BREG = BK*BN/1024;

    const int tid = threadIdx.x;
    const int warp = tid>>5, lane = tid&31;
    const int wm = warp / WARPS_N, wn = warp % WARPS_N;
    const int gid = lane>>2, qid = lane&3;
    const int bm0 = blockIdx.y*BM, bn0 = blockIdx.x*BN;

    float4 ra[AREG], rb[BREG];

    auto ldg_tile = [&](int k0){
        #pragma unroll
        for (int a=0;a<AREG;a++){
            int i = tid*4 + a*1024;
            int r = i/BK, c = i%BK;
            ra[a] = *(const float4*)(A + (size_t)(bm0+r)*K + k0 + c);
        }
        #pragma unroll
        for (int b=0;b<BREG;b++){
            int i = tid*4 + b*1024;
            int r = i/BN, c = i%BN;
            rb[b] = *(const float4*)(B + (size_t)(k0+r)*N + bn0 + c);
        }
    };
    auto sts_tile = [&](){
        #pragma unroll
        for (int a=0;a<AREG;a++){
            int i = tid*4 + a*1024;
            int r = i/BK, c = i%BK;
            uint4 p;
            p.x=f2tf32(ra[a].x); p.y=f2tf32(ra[a].y);
            p.z=f2tf32(ra[a].z); p.w=f2tf32(ra[a].w);
            *(uint4*)&As[r*PA+c] = p;
        }
        #pragma unroll
        for (int b=0;b<BREG;b++){
            int i = tid*4 + b*1024;
            int r = i/BN, c = i%BN;
            uint4 p;
            p.x=f2tf32(rb[b].x); p.y=f2tf32(rb[b].y);
            p.z=f2tf32(rb[b].z); p.w=f2tf32(rb[b].w);
            *(uint4*)&Bs[r*PB+c] = p;
        }
    };

    float acc[MT][NT][4];
    #pragma unroll
    for (int i=0;i<MT;i++)
        #pragma unroll
        for (int j=0;j<NT;j++)
            #pragma unroll
            for (int q=0;q<4;q++) acc[i][j][q]=0.f;

    ldg_tile(0);
    sts_tile();
    __syncthreads();

    const int NIT = K/BK;
    for (int it=0; it<NIT; it++){
        if (it+1 < NIT) ldg_tile((it+1)*BK);
        #pragma unroll
        for (int kk=0; kk<KT; kk++){
            unsigned af[MT][4], bf[NT][2];
            #pragma unroll
            for (int i=0;i<MT;i++){
                int r0 = wm*WM + i*16 + gid;
                int c0 = kk*8 + qid;
                af[i][0]=As[ r0   *PA + c0  ];
                af[i][1]=As[(r0+8)*PA + c0  ];
                af[i][2]=As[ r0   *PA + c0+4];
                af[i][3]=As[(r0+8)*PA + c0+4];
            }
            #pragma unroll
            for (int j=0;j<NT;j++){
                int cc = wn*WN + j*8 + gid;
                bf[j][0]=Bs[(kk*8+qid  )*PB + cc];
                bf[j][1]=Bs[(kk*8+qid+4)*PB + cc];
            }
            #pragma unroll
            for (int i=0;i<MT;i++)
                #pragma unroll
                for (int j=0;j<NT;j++){
                    asm volatile(
                        "mma.sync.aligned.m16n8k8.row.col.f32.tf32.tf32.f32 "
                        "{%0,%1,%2,%3}, {%4,%5,%6,%7}, {%8,%9}, {%0,%1,%2,%3};"
                        : "+f"(acc[i][j][0]), "+f"(acc[i][j][1]),
                          "+f"(acc[i][j][2]), "+f"(acc[i][j][3])
                        : "r"(af[i][0]), "r"(af[i][1]), "r"(af[i][2]), "r"(af[i][3]),
                          "r"(bf[j][0]), "r"(bf[j][1]));
                }
        }
        __syncthreads();
        if (it+1 < NIT){
            sts_tile();
            __syncthreads();
        }
    }
    #pragma unroll
    for (int i=0;i<MT;i++){
        int r0 = bm0 + wm*WM + i*16 + gid;
        #pragma unroll
        for (int j=0;j<NT;j++){
            int cc = bn0 + wn*WN + j*8 + qid*2;
            float b0 = BIAS ? bias[cc] : 0.f;
            float b1 = BIAS ? bias[cc+1] : 0.f;
            float2 v0, v1;
            v0.x = alpha*acc[i][j][0] + b0;
            v0.y = alpha*acc[i][j][1] + b1;
            v1.x = alpha*acc[i][j][2] + b0;
            v1.y = alpha*acc[i][j][3] + b1;
            *(float2*)(C + (size_t) r0   *N + cc) = v0;
            *(float2*)(C + (size_t)(r0+8)*N + cc) = v1;
        }
    }
}

#define HID_SMEM ((64*36 + 32*72)*4)
__global__ void __launch_bounds__(256) mma_hid_kernel(const float* __restrict__ Bw,
                                                      const float* __restrict__ bias){
    extern __shared__ unsigned dyn[];
    unsigned* As = dyn;
    unsigned* Bs = dyn + 64*36;
    mma_body<64,64,32,16,32,true>(g_acc, Bw, g_nf, HID, DIMF,
                                  0.2f, bias, As, Bs);
}

// ---------------- per layer: LN + leaky + feat(fp16)/acc update + next su ----------------
__global__ void ln_su_kernel(const float* __restrict__ linb,
                             const float* __restrict__ lng,
                             const float* __restrict__ lnb,
                             const float* __restrict__ a1next){
    int n = blockIdx.x, tid = threadIdx.x;
    float4 x = ((const float4*)g_gemm)[(size_t)n*256+tid];
    float4 bb = ((const float4*)linb)[tid];
    x.x+=bb.x; x.y+=bb.y; x.z+=bb.z; x.w+=bb.w;
    __shared__ float sm[32];
    float s = x.x+x.y+x.z+x.w;
    s = block_reduce_256(s, sm);
    float mu = s*(1.f/1024.f);
    float d0=x.x-mu, d1=x.y-mu, d2=x.z-mu, d3=x.w-mu;
    float q = d0*d0+d1*d1+d2*d2+d3*d3;
    q = block_reduce_256(q, sm);
    float r = rsqrtf(q*(1.f/1024.f)+EPSV);
    float4 gg = ((const float4*)lng)[tid];
    float4 b2 = ((const float4*)lnb)[tid];
    float4 y;
    y.x = lk(gg.x*d0*r + b2.x);
    y.y = lk(gg.y*d1*r + b2.y);
    y.z = lk(gg.z*d2*r + b2.z);
    y.w = lk(gg.w*d3*r + b2.w);
    __half2 h0 = __floats2half2_rn(y.x, y.y);
    __half2 h1 = __floats2half2_rn(y.z, y.w);
    __half2* fd = (__half2*)(g_feath + (size_t)n*DIMF + tid*4);
    fd[0]=h0; fd[1]=h1;
    float4 a = ((float4*)g_acc)[(size_t)n*256+tid];
    a.x+=y.x; a.y+=y.y; a.z+=y.z; a.w+=y.w;
    ((float4*)g_acc)[(size_t)n*256+tid] = a;
    if (a1next){
        float4 av = ((const float4*)a1next)[tid];
        float p = y.x*av.x + y.y*av.y + y.z*av.z + y.w*av.w;
        p = block_reduce_256(p, sm);
        if (tid==0){ g_su[n]=p; atomicMaxF(&g_sumax, p); }
    }
}

// ---------------- surface path ----------------
__global__ void surf_lin_kernel(const float* __restrict__ sf,
                                const float* __restrict__ W,
                                const float* __restrict__ b){
    int c  = threadIdx.x & 63;
    int ry = threadIdx.x >> 6;
    int row0 = blockIdx.x * 64;
    float w0=W[c], w1=W[64+c], w2=W[128+c], bc=b[c];
    float ls=0.f, lss=0.f;
    for (int r=ry; r<64; r+=4){
        int row = row0 + r;
        float x0=sf[row*3], x1=sf[row*3+1], x2=sf[row*3+2];
        float y = fmaf(x0,w0, fmaf(x1,w1, fmaf(x2,w2, bc)));
        g_surfy[row*64+c]=y; ls+=y; lss+=y*y;
    }
    __shared__ float ss[256], sq[256];
    ss[threadIdx.x]=ls; sq[threadIdx.x]=lss;
    __syncthreads();
    if (ry==0){
        float t  = ss[c]+ss[64+c]+ss[128+c]+ss[192+c];
        float t2 = sq[c]+sq[64+c]+sq[128+c]+sq[192+c];
        atomicAdd(&g_stats[c], t);
        atomicAdd(&g_stats[64+c], t2);
    }
}

__global__ void finalize_stats_kernel(int which, float n){
    float* st = which ? g_stats2 : g_stats;
    int c = threadIdx.x;
    float mu  = st[c] / n;
    float var = st[64+c]/n - mu*mu;
    st[c]   = mu;
    st[64+c]= rsqrtf(fmaxf(var,0.f)+EPSV);
}

__global__ void surf_norm_scatter_kernel(const int* __restrict__ surf_res,
                                         const float* __restrict__ g,
                                         const float* __restrict__ beta){
    int idx = blockIdx.x*256 + threadIdx.x;
    int row = idx >> 6, c = idx & 63;
    float y = g_surfy[idx];
    float v = lk(g[c]*(y - g_stats[c])*g_stats[64+c] + beta[c]);
    int t = surf_res[row];
    atomicAdd(&g_ressum[t*64 + c], v);
    if (c==0) atomicAdd(&g_rescnt[t], 1.f);
}

// ---------------- final heads ----------------
__global__ void prot_kernel(const float* __restrict__ g,
                            const float* __restrict__ b,
                            float* __restrict__ out){
    int gr = blockIdx.x;
    int tid = threadIdx.x;
    int c = tid & 63, chunk = tid >> 6;
    const float* base = g_nf + (size_t)gr*512*64;
    float s = 0.f;
    for (int r=chunk*128; r<(chunk+1)*128; r++) s += base[r*64+c];
    __shared__ float part[256];
    part[tid]=s; __syncthreads();
    if (chunk==0){
        float x = (part[c]+part[64+c]+part[128+c]+part[192+c])*(1.f/512.f);
        __shared__ float sm[64];
        __shared__ float s_mu, s_r;
        sm[c]=x; __syncthreads();
        if (c==0){ float t=0.f; for (int i=0;i<64;i++) t+=sm[i]; s_mu=t*(1.f/64.f); }
        __syncthreads();
        float d = x - s_mu;
        sm[c]=d*d; __syncthreads();
        if (c==0){ float t=0.f; for (int i=0;i<64;i++) t+=sm[i]; s_r=rsqrtf(t*(1.f/64.f)+EPSV); }
        __syncthreads();
        out[gr*64+c] = lk(g[c]*d*s_r + b[c]);
    }
}

__global__ void __launch_bounds__(256) ns_a_kernel(const int* __restrict__ uniq,
                            const float* __restrict__ dw,
                            const float* __restrict__ db){
    __shared__ float s_wd[128*64];
    __shared__ float z_s[4][128];
    int tid = threadIdx.x;
    int c = tid & 63, rq = tid >> 6;
    for (int i=tid; i<128*64; i+=256) s_wd[i]=dw[i];
    float bc = db[c];
    float ls=0.f, lss=0.f;
    __syncthreads();
    int row0 = blockIdx.x*16;
    for (int rr=rq; rr<16; rr+=4){
        int row = row0 + rr;
        if (row < NUNIQ){
            int u = uniq[row];
            z_s[rq][c]    = g_nf[(size_t)u*64 + c];
            z_s[rq][64+c] = g_ressum[(size_t)u*64 + c] / fmaxf(g_rescnt[u], 1.f);
        }
        __syncthreads();
        if (row < NUNIQ){
            float y = bc;
            #pragma unroll 8
            for (int k=0;k<128;k++) y = fmaf(z_s[rq][k], s_wd[k*64+c], y);
            g_y2[(size_t)row*64+c] = y;
            ls += y; lss += y*y;
        }
        __syncthreads();
    }
    atomicAdd(&g_stats2[c], ls);
    atomicAdd(&g_stats2[64+c], lss);
}

__global__ void ns_norm_scatter_kernel(const int* __restrict__ res_batch,
                                       const float* __restrict__ g,
                                       const float* __restrict__ beta){
    int idx = blockIdx.x*256 + threadIdx.x;
    if (idx >= NUNIQ*HID) return;
    int row = idx >> 6, c = idx & 63;
    float y = g_y2[idx];
    float v = lk(g[c]*(y - g_stats2[c])*g_stats2[64+c] + beta[c]);
    int t = res_batch[row];
    atomicAdd(&g_nssum[t*64 + c], v);
    if (c==0) atomicAdd(&g_nscnt[t], 1.f);
}

__global__ void ns_final_kernel(const float* __restrict__ bng,
                                const float* __restrict__ bnb,
                                float* __restrict__ out){
    int tid = threadIdx.x;
    int gr = tid >> 6, c = tid & 63;
    float v = g_nssum[tid] / fmaxf(g_nscnt[gr], 1.f);
    __shared__ float sm[1024];
    __shared__ float s_mu[64], s_r[64];
    sm[tid]=v; __syncthreads();
    if (gr==0){
        float t=0.f, t2=0.f;
        for (int r=0;r<16;r++){ float x=sm[r*64+c]; t+=x; t2+=x*x; }
        float mu = t*(1.f/16.f);
        s_mu[c]=mu;
        s_r[c]=rsqrtf(fmaxf(t2*(1.f/16.f)-mu*mu,0.f)+EPSV);
    }
    __syncthreads();
    out[16*64 + tid] = lk(bng[c]*(v - s_mu[c])*s_r[c] + bnb[c]);
}

// ---------------- host ----------------
extern "C" void kernel_launch(void* const* d_in, const int* in_sizes, int n_in,
                              void* d_out, int out_size){
    const int*   ei         = (const int*)  d_in[0];
    const float* n_feats    = (const float*)d_in[1];
    const float* surf_feats = (const float*)d_in[3];
    const int*   surf_res   = (const int*)  d_in[4];
    const int*   res_batch  = (const int*)  d_in[5];
    const int*   uniq       = (const int*)  d_in[6];
    const float* surf_up_w  = (const float*)d_in[7];
    const float* surf_up_b  = (const float*)d_in[8];
    const float* surf_up_g  = (const float*)d_in[9];
    const float* surf_up_be = (const float*)d_in[10];
    const float* a_w        = (const float*)d_in[11];
    const float* lin_w      = (const float*)d_in[12];
    const float* lin_b      = (const float*)d_in[13];
    const float* ln_g       = (const float*)d_in[14];
    const float* ln_b       = (const float*)d_in[15];
    const float* hid_w      = (const float*)d_in[16];
    const float* hid_b      = (const float*)d_in[17];
    const float* down_w     = (const float*)d_in[18];
    const float* down_b     = (const float*)d_in[19];
    const float* down_g     = (const float*)d_in[20];
    const float* down_be    = (const float*)d_in[21];
    const float* prot_ln_g  = (const float*)d_in[22];
    const float* prot_ln_b  = (const float*)d_in[23];
    const float* surf_bn_g  = (const float*)d_in[24];
    const float* surf_bn_b  = (const float*)d_in[25];
    float* out = (float*)d_out;

    cudaFuncSetAttribute(mma_main_kernel,
                         cudaFuncAttributeMaxDynamicSharedMemorySize, MAIN_SMEM);
    cudaFuncSetAttribute(mma_hid_kernel,
                         cudaFuncAttributeMaxDynamicSharedMemorySize, HID_SMEM);

    zero_kernel<<<(NNODES*HID)/256, 256>>>();                       // 1
    degfill_kernel<<<1, 1024>>>(ei);                                // 2
    init_su_kernel<<<NNODES, 256>>>(n_feats, a_w, lin_w);           // 3

    for (int l=0; l<4; l++){
        smagg_kernel<<<NNODES, 256>>>();                            // 4 <- profiled (l=0)
        mma_main_kernel<<<dim3(DIMF/128, NNODES/128), 256, MAIN_SMEM>>>(l);
        const float* a1n = (l<3) ? (a_w + (size_t)(l+1)*2*DIMF) : nullptr;
        ln_su_kernel<<<NNODES, 256>>>(lin_b + (size_t)l*DIMF,
                                      ln_g + (size_t)l*DIMF,
                                      ln_b + (size_t)l*DIMF, a1n);
    }

    mma_hid_kernel<<<dim3(1, NNODES/64), 256, HID_SMEM>>>(hid_w, hid_b);
    prot_kernel<<<NGRAPH, 256>>>(prot_ln_g, prot_ln_b, out);

    surf_lin_kernel<<<NSURF/64, 256>>>(surf_feats, surf_up_w, surf_up_b);
    finalize_stats_kernel<<<1,64>>>(0, (float)NSURF);
    surf_norm_scatter_kernel<<<(NSURF*HID)/256, 256>>>(surf_res, surf_up_g, surf_up_be);

    ns_a_kernel<<<(NUNIQ+15)/16, 256>>>(uniq, down_w, down_b);
    finalize_stats_kernel<<<1,64>>>(1, (float)NUNIQ);
    ns_norm_scatter_kernel<<<(NUNIQ*HID+255)/256, 256>>>(res_batch, down_g, down_be);
    ns_final_kernel<<<1,1024>>>(surf_bn_g, surf_bn_b, out);
}

// round 16
// speedup vs baseline: 1.6646x; 1.0523x over previous
#include <cuda_runtime.h>
#include <cuda_fp16.h>
#include <cstdint>
#include <math.h>

#define NNODES 8192
#define NEDGES 65536
#define NSURF  40000
#define NUNIQ  6000
#define NGRAPH 16
#define DIMF   1024
#define HID    64
#define EPSV   1e-5f
#define SLOPE  0.01f

// ---------------- scratch (device globals; referenced ONLY in device code) ----------------
__device__ __half   g_feath[NNODES*DIMF];
__device__ float    g_acc [NNODES*DIMF];
__device__ __half   g_aggh[NNODES*DIMF];
__device__ __half2  g_bwh [4*512*1024];
__device__ float    g_gemm[NNODES*DIMF];
__device__ float    g_surfy[NSURF*HID];
__device__ float    g_ressum[NNODES*HID];
__device__ float    g_rescnt[NNODES];
__device__ float    g_su[NNODES];
__device__ float    g_sumax;
__device__ int      g_csru[NEDGES];
__device__ int      g_rowptr[NNODES+1];
__device__ float    g_stats [2*HID];   // raw: sum, sumsq (finalize inlined in consumers)
__device__ float    g_stats2[2*HID];
__device__ float    g_nf[NNODES*HID];
__device__ float    g_y2[NUNIQ*HID];
__device__ float    g_nssum[NGRAPH*HID];
__device__ float    g_nscnt[NGRAPH];

__device__ __forceinline__ float lk(float x){ return x >= 0.f ? x : SLOPE*x; }

__device__ __forceinline__ unsigned f2tf32(float f){
    unsigned r;
    asm("cvt.rna.tf32.f32 %0, %1;" : "=r"(r) : "f"(f));
    return r;
}

__device__ __forceinline__ void atomicMaxF(float* a, float v){
    int old = __float_as_int(*a);
    while (__int_as_float(old) < v){
        int assumed = old;
        old = atomicCAS((int*)a, assumed, __float_as_int(v));
        if (old == assumed) break;
    }
}

__device__ __forceinline__ float block_reduce_256(float v, float* sm){
    #pragma unroll
    for (int o=16;o>0;o>>=1) v += __shfl_xor_sync(0xffffffffu, v, o);
    int warp = threadIdx.x>>5, lane = threadIdx.x&31;
    if (lane==0) sm[warp]=v;
    __syncthreads();
    if (warp==0){
        v = (lane<8)? sm[lane] : 0.f;
        #pragma unroll
        for (int o=4;o>0;o>>=1) v += __shfl_xor_sync(0xffffffffu, v, o);
        if (lane==0) sm[0]=v;
    }
    __syncthreads();
    float r = sm[0];
    __syncthreads();
    return r;
}

__device__ __forceinline__ float block_reduce_128(float v, float* sm){
    #pragma unroll
    for (int o=16;o>0;o>>=1) v += __shfl_xor_sync(0xffffffffu, v, o);
    int warp = threadIdx.x>>5, lane = threadIdx.x&31;
    if (lane==0) sm[warp]=v;
    __syncthreads();
    if (warp==0){
        v = (lane<4)? sm[lane] : 0.f;
        #pragma unroll
        for (int o=2;o>0;o>>=1) v += __shfl_xor_sync(0xffffffffu, v, o);
        if (lane==0) sm[0]=v;
    }
    __syncthreads();
    float r = sm[0];
    __syncthreads();
    return r;
}

// ---------------- launch 1: zeroing ----------------
__global__ void zero_kernel(){
    int i = blockIdx.x*256 + threadIdx.x;
    if (i < NNODES*HID) g_ressum[i] = 0.f;
    if (i < NNODES) g_rescnt[i]=0.f;
    if (i < 2*HID){ g_stats[i]=0.f; g_stats2[i]=0.f; }
    if (i < NGRAPH*HID) g_nssum[i]=0.f;
    if (i < NGRAPH) g_nscnt[i]=0.f;
}

// ---------------- launch 2: fused degree histogram + scan + CSR fill ----------------
__global__ void degfill_kernel(const int* __restrict__ ei){
    __shared__ int cnt[NNODES];
    __shared__ int sm[1024];
    int tid = threadIdx.x;
    if (tid==0) g_sumax = -1e30f;
    for (int i=tid; i<NNODES; i+=1024) cnt[i]=0;
    __syncthreads();
    for (int e=tid; e<NEDGES; e+=1024) atomicAdd(&cnt[ei[NEDGES+e]], 1);
    __syncthreads();
    int base = tid*8;
    int loc[8]; int s=0;
    #pragma unroll
    for (int j=0;j<8;j++){ loc[j]=s; s += cnt[base+j]; }
    sm[tid]=s; __syncthreads();
    for (int off=1; off<1024; off<<=1){
        int t = (tid>=off) ? sm[tid-off] : 0;
        __syncthreads();
        sm[tid]+=t;
        __syncthreads();
    }
    int excl = sm[tid]-s;
    int st[8];
    #pragma unroll
    for (int j=0;j<8;j++){ st[j] = excl + loc[j]; g_rowptr[base+j] = st[j]; }
    if (tid==1023) g_rowptr[NNODES] = sm[1023];
    __syncthreads();
    #pragma unroll
    for (int j=0;j<8;j++) cnt[base+j] = st[j];
    __syncthreads();
    for (int e=tid; e<NEDGES; e+=1024){
        int v = ei[NEDGES+e];
        int p = atomicAdd(&cnt[v], 1);
        g_csru[p] = ei[e];
    }
}

// ---------------- launch 3: init copy + su(layer0) + weight->fp16 pair conversion ----------------
__global__ void init_su_kernel(const float* __restrict__ nf,
                               const float* __restrict__ a1,
                               const float* __restrict__ lw){
    int n = blockIdx.x, tid = threadIdx.x;
    float4 v = ((const float4*)nf)[(size_t)n*256+tid];
    __half2 f0 = __floats2half2_rn(v.x, v.y);
    __half2 f1 = __floats2half2_rn(v.z, v.w);
    __half2* fd = (__half2*)(g_feath + (size_t)n*DIMF + tid*4);
    fd[0]=f0; fd[1]=f1;
    ((float4*)g_acc)[(size_t)n*256+tid]=v;
    {
        size_t idx = (size_t)n*256 + tid;
        int l   = (int)(idx >> 19);
        int rem = (int)(idx & 524287);
        int k2  = rem >> 10;
        int nn  = rem & 1023;
        const float* base = lw + ((size_t)l << 20);
        float v0 = base[(size_t)(2*k2  )*1024 + nn];
        float v1 = base[(size_t)(2*k2+1)*1024 + nn];
        g_bwh[idx] = __floats2half2_rn(v0, v1);
    }
    float4 a = ((const float4*)a1)[tid];
    float p = v.x*a.x + v.y*a.y + v.z*a.z + v.w*a.w;
    __shared__ float sm[32];
    p = block_reduce_256(p, sm);
    if (tid==0){ g_su[n]=p; atomicMaxF(&g_sumax, p); }
}

// ---------------- launch 4 (profiled): fused edge-softmax + aggregate ----------------
// 128 threads/node; each thread covers 8 cols via uint4 (8 halves).
__global__ void __launch_bounds__(128) smagg_kernel(){
    int n = blockIdx.x, tid = threadIdx.x;
    int s = g_rowptr[n], e = g_rowptr[n+1];
    __shared__ float s_w[128]; __shared__ int s_u[128];
    __shared__ float red[32];
    float m = g_sumax;
    float lsum = 0.f;
    float acc[8];
    #pragma unroll
    for (int i=0;i<8;i++) acc[i]=0.f;
    for (int base=s; base<e; base+=128){
        int j = base + tid;
        if (j<e){
            int u = g_csru[j];
            float ex = __expf(g_su[u] - m);
            s_w[tid]=ex; s_u[tid]=u; lsum += ex;
        }
        __syncthreads();
        int cnt = min(128, e-base);
        for (int t=0;t<cnt;t++){
            float wv = s_w[t]; int u = s_u[t];
            uint4 hv = *(const uint4*)(g_feath + (size_t)u*DIMF + tid*8);
            float2 f0 = __half22float2(*(const __half2*)&hv.x);
            float2 f1 = __half22float2(*(const __half2*)&hv.y);
            float2 f2 = __half22float2(*(const __half2*)&hv.z);
            float2 f3 = __half22float2(*(const __half2*)&hv.w);
            acc[0]+=wv*f0.x; acc[1]+=wv*f0.y;
            acc[2]+=wv*f1.x; acc[3]+=wv*f1.y;
            acc[4]+=wv*f2.x; acc[5]+=wv*f2.y;
            acc[6]+=wv*f3.x; acc[7]+=wv*f3.y;
        }
        __syncthreads();
    }
    float total = block_reduce_128(lsum, red);
    if (total > 0.f){
        float inv = 1.f/total;
        #pragma unroll
        for (int i=0;i<8;i++) acc[i]*=inv;
    }
    uint4 o;
    *(__half2*)&o.x = __floats2half2_rn(acc[0], acc[1]);
    *(__half2*)&o.y = __floats2half2_rn(acc[2], acc[3]);
    *(__half2*)&o.z = __floats2half2_rn(acc[4], acc[5]);
    *(__half2*)&o.w = __floats2half2_rn(acc[6], acc[7]);
    *(uint4*)(g_aggh + (size_t)n*DIMF + tid*8) = o;
}

// ---------------- launch 5: main fp16 GEMM (mma.sync m16n8k16) ----------------
#define STG  3
#define PA2  20
#define PB2  136
#define ASZ2 (128*PA2)
#define BSZ2 (16*PB2)
#define MAIN_SMEM (STG*(ASZ2+BSZ2)*4)

__global__ void __launch_bounds__(256,2) mma_main_kernel(int layer){
    extern __shared__ unsigned dyn[];
    unsigned* AsB = dyn;
    unsigned* BsB = dyn + STG*ASZ2;
    const __half*  A = g_aggh;
    const unsigned* B = (const unsigned*)(g_bwh + (size_t)layer*524288);

    const int tid = threadIdx.x;
    const int warp = tid>>5, lane = tid&31;
    const int wm = warp>>2, wn = warp&3;
    const int gid = lane>>2, qid = lane&3;
    const int bm0 = blockIdx.y*128, bn0 = blockIdx.x*128;

    if (blockIdx.x==0 && blockIdx.y==0 && tid==0) g_sumax = -1e30f;

    auto issue = [&](int it){
        unsigned* As = AsB + (it%STG)*ASZ2;
        unsigned* Bs = BsB + (it%STG)*BSZ2;
        int k0 = it*32;
        int k20 = it*16;
        #pragma unroll
        for (int a=0;a<2;a++){
            int chunk = tid + a*256;
            int row = chunk>>2, c16 = chunk&3;
            unsigned dst = (unsigned)__cvta_generic_to_shared(&As[row*PA2 + c16*4]);
            asm volatile("cp.async.cg.shared.global [%0], [%1], 16;"
                         :: "r"(dst), "l"(A + (size_t)(bm0+row)*DIMF + k0 + c16*8));
        }
        #pragma unroll
        for (int b=0;b<2;b++){
            int chunk = tid + b*256;
            int row = chunk>>5, c4 = chunk&31;
            unsigned dst = (unsigned)__cvta_generic_to_shared(&Bs[row*PB2 + c4*4]);
            asm volatile("cp.async.cg.shared.global [%0], [%1], 16;"
                         :: "r"(dst), "l"(B + (size_t)(k20+row)*1024 + bn0 + c4*4));
        }
        asm volatile("cp.async.commit_group;" ::: "memory");
    };

    float acc[4][4][4];
    #pragma unroll
    for (int i=0;i<4;i++)
        #pragma unroll
        for (int j=0;j<4;j++)
            #pragma unroll
            for (int q=0;q<4;q++) acc[i][j][q]=0.f;

    issue(0); issue(1);

    const int NIT = DIMF/32;
    for (int it=0; it<NIT; it++){
        asm volatile("cp.async.wait_group 1;" ::: "memory");
        __syncthreads();
        if (it+2 < NIT) issue(it+2);
        const unsigned* curA = AsB + (it%STG)*ASZ2;
        const unsigned* curB = BsB + (it%STG)*BSZ2;
        #pragma unroll
        for (int kk=0; kk<2; kk++){
            unsigned af[4][4], bf[4][2];
            #pragma unroll
            for (int i=0;i<4;i++){
                int r0 = wm*64 + i*16 + gid;
                int c0 = kk*8 + qid;
                af[i][0]=curA[ r0   *PA2 + c0  ];
                af[i][1]=curA[(r0+8)*PA2 + c0  ];
                af[i][2]=curA[ r0   *PA2 + c0+4];
                af[i][3]=curA[(r0+8)*PA2 + c0+4];
            }
            #pragma unroll
            for (int j=0;j<4;j++){
                int cc = wn*32 + j*8 + gid;
                bf[j][0]=curB[(kk*8+qid  )*PB2 + cc];
                bf[j][1]=curB[(kk*8+qid+4)*PB2 + cc];
            }
            #pragma unroll
            for (int i=0;i<4;i++)
                #pragma unroll
                for (int j=0;j<4;j++){
                    asm volatile(
                        "mma.sync.aligned.m16n8k16.row.col.f32.f16.f16.f32 "
                        "{%0,%1,%2,%3}, {%4,%5,%6,%7}, {%8,%9}, {%0,%1,%2,%3};"
                        : "+f"(acc[i][j][0]), "+f"(acc[i][j][1]),
                          "+f"(acc[i][j][2]), "+f"(acc[i][j][3])
                        : "r"(af[i][0]), "r"(af[i][1]), "r"(af[i][2]), "r"(af[i][3]),
                          "r"(bf[j][0]), "r"(bf[j][1]));
                }
        }
    }
    #pragma unroll
    for (int i=0;i<4;i++){
        int r0 = bm0 + wm*64 + i*16 + gid;
        #pragma unroll
        for (int j=0;j<4;j++){
            int cc = bn0 + wn*32 + j*8 + qid*2;
            float2 v0, v1;
            v0.x = acc[i][j][0]; v0.y = acc[i][j][1];
            v1.x = acc[i][j][2]; v1.y = acc[i][j][3];
            *(float2*)(g_gemm + (size_t) r0   *DIMF + cc) = v0;
            *(float2*)(g_gemm + (size_t)(r0+8)*DIMF + cc) = v1;
        }
    }
}

// ---------------- hid GEMM (small; tf32 register-staged path) ----------------
template<int BM,int BN,int BK,int WM,int WN,bool BIAS>
__device__ __forceinline__ void mma_body(
        const float* __restrict__ A, const float* __restrict__ B,
        float* __restrict__ C, int N, int K,
        float alpha, const float* __restrict__ bias,
        unsigned* As, unsigned* Bs){
    constexpr int MT = WM/16, NT = WN/8, KT = BK/8;
    constexpr int WARPS_N = BN/WN;
    constexpr int PA = BK+4;
    constexpr int PB = BN+8;
    constexpr int AREG = BM*BK/1024;
    constexpr int BREG = BK*BN/1024;

    const int tid = threadIdx.x;
    const int warp = tid>>5, lane = tid&31;
    const int wm = warp / WARPS_N, wn = warp % WARPS_N;
    const int gid = lane>>2, qid = lane&3;
    const int bm0 = blockIdx.y*BM, bn0 = blockIdx.x*BN;

    float4 ra[AREG], rb[BREG];

    auto ldg_tile = [&](int k0){
        #pragma unroll
        for (int a=0;a<AREG;a++){
            int i = tid*4 + a*1024;
            int r = i/BK, c = i%BK;
            ra[a] = *(const float4*)(A + (size_t)(bm0+r)*K + k0 + c);
        }
        #pragma unroll
        for (int b=0;b<BREG;b++){
            int i = tid*4 + b*1024;
            int r = i/BN, c = i%BN;
            rb[b] = *(const float4*)(B + (size_t)(k0+r)*N + bn0 + c);
        }
    };
    auto sts_tile = [&](){
        #pragma unroll
        for (int a=0;a<AREG;a++){
            int i = tid*4 + a*1024;
            int r = i/BK, c = i%BK;
            uint4 p;
            p.x=f2tf32(ra[a].x); p.y=f2tf32(ra[a].y);
            p.z=f2tf32(ra[a].z); p.w=f2tf32(ra[a].w);
            *(uint4*)&As[r*PA+c] = p;
        }
        #pragma unroll
        for (int b=0;b<BREG;b++){
            int i = tid*4 + b*1024;
            int r = i/BN, c = i%BN;
            uint4 p;
            p.x=f2tf32(rb[b].x); p.y=f2tf32(rb[b].y);
            p.z=f2tf32(rb[b].z); p.w=f2tf32(rb[b].w);
            *(uint4*)&Bs[r*PB+c] = p;
        }
    };

    float acc[MT][NT][4];
    #pragma unroll
    for (int i=0;i<MT;i++)
        #pragma unroll
        for (int j=0;j<NT;j++)
            #pragma unroll
            for (int q=0;q<4;q++) acc[i][j][q]=0.f;

    ldg_tile(0);
    sts_tile();
    __syncthreads();

    const int NIT = K/BK;
    for (int it=0; it<NIT; it++){
        if (it+1 < NIT) ldg_tile((it+1)*BK);
        #pragma unroll
        for (int kk=0; kk<KT; kk++){
            unsigned af[MT][4], bf[NT][2];
            #pragma unroll
            for (int i=0;i<MT;i++){
                int r0 = wm*WM + i*16 + gid;
                int c0 = kk*8 + qid;
                af[i][0]=As[ r0   *PA + c0  ];
                af[i][1]=As[(r0+8)*PA + c0  ];
                af[i][2]=As[ r0   *PA + c0+4];
                af[i][3]=As[(r0+8)*PA + c0+4];
            }
            #pragma unroll
            for (int j=0;j<NT;j++){
                int cc = wn*WN + j*8 + gid;
                bf[j][0]=Bs[(kk*8+qid  )*PB + cc];
                bf[j][1]=Bs[(kk*8+qid+4)*PB + cc];
            }
            #pragma unroll
            for (int i=0;i<MT;i++)
                #pragma unroll
                for (int j=0;j<NT;j++){
                    asm volatile(
                        "mma.sync.aligned.m16n8k8.row.col.f32.tf32.tf32.f32 "
                        "{%0,%1,%2,%3}, {%4,%5,%6,%7}, {%8,%9}, {%0,%1,%2,%3};"
                        : "+f"(acc[i][j][0]), "+f"(acc[i][j][1]),
                          "+f"(acc[i][j][2]), "+f"(acc[i][j][3])
                        : "r"(af[i][0]), "r"(af[i][1]), "r"(af[i][2]), "r"(af[i][3]),
                          "r"(bf[j][0]), "r"(bf[j][1]));
                }
        }
        __syncthreads();
        if (it+1 < NIT){
            sts_tile();
            __syncthreads();
        }
    }
    #pragma unroll
    for (int i=0;i<MT;i++){
        int r0 = bm0 + wm*WM + i*16 + gid;
        #pragma unroll
        for (int j=0;j<NT;j++){
            int cc = bn0 + wn*WN + j*8 + qid*2;
            float b0 = BIAS ? bias[cc] : 0.f;
            float b1 = BIAS ? bias[cc+1] : 0.f;
            float2 v0, v1;
            v0.x = alpha*acc[i][j][0] + b0;
            v0.y = alpha*acc[i][j][1] + b1;
            v1.x = alpha*acc[i][j][2] + b0;
            v1.y = alpha*acc[i][j][3] + b1;
            *(float2*)(C + (size_t) r0   *N + cc) = v0;
            *(float2*)(C + (size_t)(r0+8)*N + cc) = v1;
        }
    }
}

#define HID_SMEM ((64*36 + 32*72)*4)
__global__ void __launch_bounds__(256) mma_hid_kernel(const float* __restrict__ Bw,
                                                      const float* __restrict__ bias){
    extern __shared__ unsigned dyn[];
    unsigned* As = dyn;
    unsigned* Bs = dyn + 64*36;
    mma_body<64,64,32,16,32,true>(g_acc, Bw, g_nf, HID, DIMF,
                                  0.2f, bias, As, Bs);
}

// ---------------- per layer: LN + leaky + feat(fp16)/acc update + next su ----------------
__global__ void ln_su_kernel(const float* __restrict__ linb,
                             const float* __restrict__ lng,
                             const float* __restrict__ lnb,
                             const float* __restrict__ a1next){
    int n = blockIdx.x, tid = threadIdx.x;
    float4 x = ((const float4*)g_gemm)[(size_t)n*256+tid];
    float4 bb = ((const float4*)linb)[tid];
    x.x+=bb.x; x.y+=bb.y; x.z+=bb.z; x.w+=bb.w;
    __shared__ float sm[32];
    float s = x.x+x.y+x.z+x.w;
    s = block_reduce_256(s, sm);
    float mu = s*(1.f/1024.f);
    float d0=x.x-mu, d1=x.y-mu, d2=x.z-mu, d3=x.w-mu;
    float q = d0*d0+d1*d1+d2*d2+d3*d3;
    q = block_reduce_256(q, sm);
    float r = rsqrtf(q*(1.f/1024.f)+EPSV);
    float4 gg = ((const float4*)lng)[tid];
    float4 b2 = ((const float4*)lnb)[tid];
    float4 y;
    y.x = lk(gg.x*d0*r + b2.x);
    y.y = lk(gg.y*d1*r + b2.y);
    y.z = lk(gg.z*d2*r + b2.z);
    y.w = lk(gg.w*d3*r + b2.w);
    __half2 h0 = __floats2half2_rn(y.x, y.y);
    __half2 h1 = __floats2half2_rn(y.z, y.w);
    __half2* fd = (__half2*)(g_feath + (size_t)n*DIMF + tid*4);
    fd[0]=h0; fd[1]=h1;
    float4 a = ((float4*)g_acc)[(size_t)n*256+tid];
    a.x+=y.x; a.y+=y.y; a.z+=y.z; a.w+=y.w;
    ((float4*)g_acc)[(size_t)n*256+tid] = a;
    if (a1next){
        float4 av = ((const float4*)a1next)[tid];
        float p = y.x*av.x + y.y*av.y + y.z*av.z + y.w*av.w;
        p = block_reduce_256(p, sm);
        if (tid==0){ g_su[n]=p; atomicMaxF(&g_sumax, p); }
    }
}

// ---------------- surface path ----------------
__global__ void surf_lin_kernel(const float* __restrict__ sf,
                                const float* __restrict__ W,
                                const float* __restrict__ b){
    int c  = threadIdx.x & 63;
    int ry = threadIdx.x >> 6;
    int row0 = blockIdx.x * 64;
    float w0=W[c], w1=W[64+c], w2=W[128+c], bc=b[c];
    float ls=0.f, lss=0.f;
    for (int r=ry; r<64; r+=4){
        int row = row0 + r;
        float x0=sf[row*3], x1=sf[row*3+1], x2=sf[row*3+2];
        float y = fmaf(x0,w0, fmaf(x1,w1, fmaf(x2,w2, bc)));
        g_surfy[row*64+c]=y; ls+=y; lss+=y*y;
    }
    __shared__ float ss[256], sq[256];
    ss[threadIdx.x]=ls; sq[threadIdx.x]=lss;
    __syncthreads();
    if (ry==0){
        float t  = ss[c]+ss[64+c]+ss[128+c]+ss[192+c];
        float t2 = sq[c]+sq[64+c]+sq[128+c]+sq[192+c];
        atomicAdd(&g_stats[c], t);
        atomicAdd(&g_stats[64+c], t2);
    }
}

// stats finalization inlined (raw sums -> mu/invstd per thread)
__global__ void surf_norm_scatter_kernel(const int* __restrict__ surf_res,
                                         const float* __restrict__ g,
                                         const float* __restrict__ beta){
    int idx = blockIdx.x*256 + threadIdx.x;
    int row = idx >> 6, c = idx & 63;
    float mu  = g_stats[c] * (1.f/NSURF);
    float var = g_stats[64+c]*(1.f/NSURF) - mu*mu;
    float inv = rsqrtf(fmaxf(var,0.f)+EPSV);
    float y = g_surfy[idx];
    float v = lk(g[c]*(y - mu)*inv + beta[c]);
    int t = surf_res[row];
    atomicAdd(&g_ressum[t*64 + c], v);
    if (c==0) atomicAdd(&g_rescnt[t], 1.f);
}

// ---------------- final heads ----------------
__global__ void prot_kernel(const float* __restrict__ g,
                            const float* __restrict__ b,
                            float* __restrict__ out){
    int gr = blockIdx.x;
    int tid = threadIdx.x;
    int c = tid & 63, chunk = tid >> 6;
    const float* base = g_nf + (size_t)gr*512*64;
    float s = 0.f;
    for (int r=chunk*128; r<(chunk+1)*128; r++) s += base[r*64+c];
    __shared__ float part[256];
    part[tid]=s; __syncthreads();
    if (chunk==0){
        float x = (part[c]+part[64+c]+part[128+c]+part[192+c])*(1.f/512.f);
        __shared__ float sm[64];
        __shared__ float s_mu, s_r;
        sm[c]=x; __syncthreads();
        if (c==0){ float t=0.f; for (int i=0;i<64;i++) t+=sm[i]; s_mu=t*(1.f/64.f); }
        __syncthreads();
        float d = x - s_mu;
        sm[c]=d*d; __syncthreads();
        if (c==0){ float t=0.f; for (int i=0;i<64;i++) t+=sm[i]; s_r=rsqrtf(t*(1.f/64.f)+EPSV); }
        __syncthreads();
        out[gr*64+c] = lk(g[c]*d*s_r + b[c]);
    }
}

__global__ void __launch_bounds__(256) ns_a_kernel(const int* __restrict__ uniq,
                            const float* __restrict__ dw,
                            const float* __restrict__ db){
    __shared__ float s_wd[128*64];
    __shared__ float z_s[4][128];
    int tid = threadIdx.x;
    int c = tid & 63, rq = tid >> 6;
    for (int i=tid; i<128*64; i+=256) s_wd[i]=dw[i];
    float bc = db[c];
    float ls=0.f, lss=0.f;
    __syncthreads();
    int row0 = blockIdx.x*16;
    for (int rr=rq; rr<16; rr+=4){
        int row = row0 + rr;
        if (row < NUNIQ){
            int u = uniq[row];
            z_s[rq][c]    = g_nf[(size_t)u*64 + c];
            z_s[rq][64+c] = g_ressum[(size_t)u*64 + c] / fmaxf(g_rescnt[u], 1.f);
        }
        __syncthreads();
        if (row < NUNIQ){
            float y = bc;
            #pragma unroll 8
            for (int k=0;k<128;k++) y = fmaf(z_s[rq][k], s_wd[k*64+c], y);
            g_y2[(size_t)row*64+c] = y;
            ls += y; lss += y*y;
        }
        __syncthreads();
    }
    atomicAdd(&g_stats2[c], ls);
    atomicAdd(&g_stats2[64+c], lss);
}

__global__ void ns_norm_scatter_kernel(const int* __restrict__ res_batch,
                                       const float* __restrict__ g,
                                       const float* __restrict__ beta){
    int idx = blockIdx.x*256 + threadIdx.x;
    if (idx >= NUNIQ*HID) return;
    int row = idx >> 6, c = idx & 63;
    float mu  = g_stats2[c] * (1.f/NUNIQ);
    float var = g_stats2[64+c]*(1.f/NUNIQ) - mu*mu;
    float inv = rsqrtf(fmaxf(var,0.f)+EPSV);
    float y = g_y2[idx];
    float v = lk(g[c]*(y - mu)*inv + beta[c]);
    int t = res_batch[row];
    atomicAdd(&g_nssum[t*64 + c], v);
    if (c==0) atomicAdd(&g_nscnt[t], 1.f);
}

__global__ void ns_final_kernel(const float* __restrict__ bng,
                                const float* __restrict__ bnb,
                                float* __restrict__ out){
    int tid = threadIdx.x;
    int gr = tid >> 6, c = tid & 63;
    float v = g_nssum[tid] / fmaxf(g_nscnt[gr], 1.f);
    __shared__ float sm[1024];
    __shared__ float s_mu[64], s_r[64];
    sm[tid]=v; __syncthreads();
    if (gr==0){
        float t=0.f, t2=0.f;
        for (int r=0;r<16;r++){ float x=sm[r*64+c]; t+=x; t2+=x*x; }
        float mu = t*(1.f/16.f);
        s_mu[c]=mu;
        s_r[c]=rsqrtf(fmaxf(t2*(1.f/16.f)-mu*mu,0.f)+EPSV);
    }
    __syncthreads();
    out[16*64 + tid] = lk(bng[c]*(v - s_mu[c])*s_r[c] + bnb[c]);
}

// ---------------- host ----------------
extern "C" void kernel_launch(void* const* d_in, const int* in_sizes, int n_in,
                              void* d_out, int out_size){
    const int*   ei         = (const int*)  d_in[0];
    const float* n_feats    = (const float*)d_in[1];
    const float* surf_feats = (const float*)d_in[3];
    const int*   surf_res   = (const int*)  d_in[4];
    const int*   res_batch  = (const int*)  d_in[5];
    const int*   uniq       = (const int*)  d_in[6];
    const float* surf_up_w  = (const float*)d_in[7];
    const float* surf_up_b  = (const float*)d_in[8];
    const float* surf_up_g  = (const float*)d_in[9];
    const float* surf_up_be = (const float*)d_in[10];
    const float* a_w        = (const float*)d_in[11];
    const float* lin_w      = (const float*)d_in[12];
    const float* lin_b      = (const float*)d_in[13];
    const float* ln_g       = (const float*)d_in[14];
    const float* ln_b       = (const float*)d_in[15];
    const float* hid_w      = (const float*)d_in[16];
    const float* hid_b      = (const float*)d_in[17];
    const float* down_w     = (const float*)d_in[18];
    const float* down_b     = (const float*)d_in[19];
    const float* down_g     = (const float*)d_in[20];
    const float* down_be    = (const float*)d_in[21];
    const float* prot_ln_g  = (const float*)d_in[22];
    const float* prot_ln_b  = (const float*)d_in[23];
    const float* surf_bn_g  = (const float*)d_in[24];
    const float* surf_bn_b  = (const float*)d_in[25];
    float* out = (float*)d_out;

    cudaFuncSetAttribute(mma_main_kernel,
                         cudaFuncAttributeMaxDynamicSharedMemorySize, MAIN_SMEM);
    cudaFuncSetAttribute(mma_hid_kernel,
                         cudaFuncAttributeMaxDynamicSharedMemorySize, HID_SMEM);

    zero_kernel<<<(NNODES*HID)/256, 256>>>();                       // 1
    degfill_kernel<<<1, 1024>>>(ei);                                // 2
    init_su_kernel<<<NNODES, 256>>>(n_feats, a_w, lin_w);           // 3

    for (int l=0; l<4; l++){
        smagg_kernel<<<NNODES, 128>>>();                            // 4 <- profiled (l=0)
        mma_main_kernel<<<dim3(DIMF/128, NNODES/128), 256, MAIN_SMEM>>>(l);
        const float* a1n = (l<3) ? (a_w + (size_t)(l+1)*2*DIMF) : nullptr;
        ln_su_kernel<<<NNODES, 256>>>(lin_b + (size_t)l*DIMF,
                                      ln_g + (size_t)l*DIMF,
                                      ln_b + (size_t)l*DIMF, a1n);
    }

    mma_hid_kernel<<<dim3(1, NNODES/64), 256, HID_SMEM>>>(hid_w, hid_b);
    prot_kernel<<<NGRAPH, 256>>>(prot_ln_g, prot_ln_b, out);

    surf_lin_kernel<<<NSURF/64, 256>>>(surf_feats, surf_up_w, surf_up_b);
    surf_norm_scatter_kernel<<<(NSURF*HID)/256, 256>>>(surf_res, surf_up_g, surf_up_be);

    ns_a_kernel<<<(NUNIQ+15)/16, 256>>>(uniq, down_w, down_b);
    ns_norm_scatter_kernel<<<(NUNIQ*HID+255)/256, 256>>>(res_batch, down_g, down_be);
    ns_final_kernel<<<1,1024>>>(surf_bn_g, surf_bn_b, out);
}